// round 4
// baseline (speedup 1.0000x reference)
#include <cuda_runtime.h>
#include <cstdint>
#include <cstddef>

// Fixed problem shapes (asserted by construction of the dataset):
//   x: [B, 512, 64, 64] f32, mask: [64, 64] bool.  d = 256, N = 4096.
#define BMAX   8
#define DDIM   256
#define NPIX   4096

// ---------------- scratch (device globals; zero-initialized at load) ----------
__device__ float g_Q[(size_t)BMAX * DDIM * NPIX];   // normalized latter, hole cols, d-major [b][d][qpos]
__device__ float g_K[(size_t)BMAX * DDIM * NPIX];   // normalized latter, known cols, d-major [b][d][kpos]
__device__ float g_F[(size_t)BMAX * DDIM * NPIX];   // former, known cols, d-major [b][d][kpos]
__device__ int   g_qidx[NPIX];                      // compacted hole pixel indices (global n)
__device__ int   g_pos [NPIX];                      // per-pixel position in its compacted list
__device__ int   g_isq [NPIX];                      // 1 = hole (query), 0 = known (key)
__device__ int   g_cnt [2];                         // [0]=qcnt, [1]=kcnt

// ---------------- kernel 0: deterministic mask compaction ---------------------
// One block, 128 threads. Also sniffs whether the mask buffer is bool-bytes
// (numpy bool_) or int32: reading the first N/4 words is in-bounds for both
// layouts; any word value > 1 implies packed bytes.
__global__ void k_compact(const void* __restrict__ maskp, int N)
{
    __shared__ int cq[129];
    __shared__ int s_isu8;
    const int CH = N / 128;                      // 32
    int t = threadIdx.x;

    if (t == 0) {
        const unsigned* w = (const unsigned*)maskp;
        int u8 = 0;
        for (int i = 0; i < N / 4; i++) { if (w[i] > 1u) { u8 = 1; break; } }
        s_isu8 = u8;
    }
    __syncthreads();
    const int isu8 = s_isu8;
    const unsigned char* mb = (const unsigned char*)maskp;
    const int*           mw = (const int*)maskp;

    int nq = 0;
    for (int i = t * CH; i < t * CH + CH; i++)
        nq += (isu8 ? (mb[i] != 0) : (mw[i] != 0));
    cq[t] = nq;
    __syncthreads();
    if (t == 0) {
        int acc = 0;
        for (int i = 0; i < 128; i++) { int v = cq[i]; cq[i] = acc; acc += v; }
        cq[128] = acc;
        g_cnt[0] = acc;
        g_cnt[1] = N - acc;
    }
    __syncthreads();
    int q = cq[t];
    int k = t * CH - cq[t];
    for (int i = t * CH; i < t * CH + CH; i++) {
        int f = (isu8 ? (mb[i] != 0) : (mw[i] != 0));
        if (f) { g_qidx[q] = i; g_pos[i] = q; g_isq[i] = 1; q++; }
        else   {               g_pos[i] = k; g_isq[i] = 0; k++; }
    }
}

// ---------------- kernel 1: column norms + compacted pack ---------------------
// grid (N/32, B), 256 threads. Each block handles 32 pixel-columns of one batch:
// computes inv-norm of the latter column, writes normalized values into g_Q or
// g_K (d-major, column-compacted), and former values into g_F for known cols.
__global__ void k_pack(const float* __restrict__ x)
{
    __shared__ float tile[256][33];
    __shared__ float psum[8][32];
    __shared__ float inv_s[32];
    __shared__ int   pp[32], mq[32];

    const int b  = blockIdx.y;
    const int n0 = blockIdx.x * 32;
    const int tx = threadIdx.x & 31;
    const int ty = threadIdx.x >> 5;       // 0..7

    const float* lat = x + ((size_t)b * 512 + 256) * NPIX;

    for (int r = ty; r < 256; r += 8)
        tile[r][tx] = lat[(size_t)r * NPIX + n0 + tx];
    if (threadIdx.x < 32) { pp[tx] = g_pos[n0 + tx]; mq[tx] = g_isq[n0 + tx]; }
    __syncthreads();

    float ss = 0.f;
    for (int r = ty * 32; r < ty * 32 + 32; r++) { float v = tile[r][tx]; ss += v * v; }
    psum[ty][tx] = ss;
    __syncthreads();
    if (threadIdx.x < 32) {
        float s = 0.f;
        #pragma unroll
        for (int i = 0; i < 8; i++) s += psum[i][tx];
        inv_s[tx] = 1.0f / (sqrtf(s) + 1e-8f);
    }
    __syncthreads();

    const float inv = inv_s[tx];
    const int   p   = pp[tx];
    const int   isq = mq[tx];
    float* dst = (isq ? g_Q : g_K) + (size_t)b * DDIM * NPIX + p;
    for (int r = ty; r < 256; r += 8)
        dst[(size_t)r * NPIX] = tile[r][tx] * inv;

    if (!isq) {
        const float* fm = x + (size_t)b * 512 * NPIX;
        float* df = g_F + (size_t)b * DDIM * NPIX + p;
        for (int r = ty; r < 256; r += 8)
            df[(size_t)r * NPIX] = fm[(size_t)r * NPIX + n0 + tx];
    }
}

// ---------------- kernel 2: copy former/latter, zero shift region -------------
__global__ void k_out(const float* __restrict__ x, float* __restrict__ out, int N)
{
    const size_t perB = (size_t)768 * N / 4;     // float4 per batch
    const size_t copyB = (size_t)512 * N / 4;    // float4 of copied channels
    size_t f = (size_t)blockIdx.x * 256 + threadIdx.x;
    size_t b = f / perB;
    size_t r = f % perB;
    float4 v;
    if (r < copyB) v = ((const float4*)x)[b * copyB + r];
    else           v = make_float4(0.f, 0.f, 0.f, 0.f);
    ((float4*)out)[f] = v;
}

// ---------------- kernel 3: fused flash-attention ------------------------------
// grid (N/64, B), 256 threads, dynamic smem.
// QT=64 queries resident in smem ([d][q], 64 KB). Loop 64-key tiles:
//   GEMM1  S[64x64] = Q^T K   (d-chunks of 16, float4 LDS, 4x4 reg tile)
//   online softmax (16-lane shuffle reductions)
//   GEMM2  O[64x256] += P F^T (dout-chunks of 64, float4 LDS, 4x4 reg tile)
// Epilogue: divide by l, stage through smem, coalesced scatter into hole cols.
#define SM_QS   0                         // [256][64]         16384 floats
#define SM_KS   (256 * 64)                // [16][64]           1024 floats
#define SM_PS   (SM_KS + 16 * 64)         // [64][68]           4352 floats
#define SM_FS   (SM_PS + 64 * 68)         // [64][68]           4352 floats
#define SM_FLT  (SM_FS + 64 * 68)         // total floats      26112
#define SM_BYTES (SM_FLT * 4 + 64 * 4)    // + qn[64]         104704 B

__global__ void __launch_bounds__(256)
k_attn(float* __restrict__ out)
{
    extern __shared__ float sm[];
    float* Qs = sm + SM_QS;
    float* Ks = sm + SM_KS;
    float* Ps = sm + SM_PS;
    float* Fs = sm + SM_FS;
    int*   qn = (int*)(sm + SM_FLT);

    const int b    = blockIdx.y;
    const int qcnt = g_cnt[0];
    const int kcnt = g_cnt[1];
    const int q0   = blockIdx.x * 64;
    if (q0 >= qcnt) return;

    const int tid = threadIdx.x;
    const int ti  = tid >> 4;     // 0..15  -> 4 query rows
    const int tj  = tid & 15;     // 0..15  -> 4 key cols / 4 dout rows

    // ---- load Q tile into smem, d-major [dd][q], zero rows past qcnt ----
    {
        const float* Qg = g_Q + (size_t)b * DDIM * NPIX + q0;
        #pragma unroll
        for (int i = 0; i < 16; i++) {
            int fid = tid + i * 256;           // 4096 float4 slots
            int dd  = fid >> 4;
            int qq  = (fid & 15) << 2;
            float4 v = *(const float4*)(Qg + (size_t)dd * NPIX + qq);
            int qb = q0 + qq;
            if (qb + 3 >= qcnt) {
                if (qb + 0 >= qcnt) v.x = 0.f;
                if (qb + 1 >= qcnt) v.y = 0.f;
                if (qb + 2 >= qcnt) v.z = 0.f;
                if (qb + 3 >= qcnt) v.w = 0.f;
            }
            *(float4*)(Qs + dd * 64 + qq) = v;
        }
        if (tid < 64) qn[tid] = (q0 + tid < qcnt) ? g_qidx[q0 + tid] : -1;
    }
    __syncthreads();

    float o[64];
    #pragma unroll
    for (int i = 0; i < 64; i++) o[i] = 0.f;
    float m[4], l[4];
    #pragma unroll
    for (int i = 0; i < 4; i++) { m[i] = -1e30f; l[i] = 0.f; }

    const float* Kg = g_K + (size_t)b * DDIM * NPIX;
    const float* Fg = g_F + (size_t)b * DDIM * NPIX;
    const int ntiles = (kcnt + 63) >> 6;

    for (int kt = 0; kt < ntiles; kt++) {
        const int k0 = kt << 6;

        // ---------- GEMM1: S = Q^T K ----------
        float s[4][4];
        #pragma unroll
        for (int i = 0; i < 4; i++)
            #pragma unroll
            for (int j = 0; j < 4; j++) s[i][j] = 0.f;

        #pragma unroll 1
        for (int dc = 0; dc < 256; dc += 16) {
            {   // load K chunk [16][64]
                int dd = tid >> 4;
                int kq = (tid & 15) << 2;
                float4 v = *(const float4*)(Kg + (size_t)(dc + dd) * NPIX + k0 + kq);
                *(float4*)(Ks + dd * 64 + kq) = v;
            }
            __syncthreads();
            #pragma unroll
            for (int dd = 0; dd < 16; dd++) {
                float4 qv = *(const float4*)(Qs + (dc + dd) * 64 + (ti << 2));
                float4 kv = *(const float4*)(Ks + dd * 64 + (tj << 2));
                float qa[4] = {qv.x, qv.y, qv.z, qv.w};
                float ka[4] = {kv.x, kv.y, kv.z, kv.w};
                #pragma unroll
                for (int i = 0; i < 4; i++)
                    #pragma unroll
                    for (int j = 0; j < 4; j++) s[i][j] += qa[i] * ka[j];
            }
            __syncthreads();
        }

        // mask out-of-range keys (last partial tile)
        #pragma unroll
        for (int j = 0; j < 4; j++) {
            if (k0 + (tj << 2) + j >= kcnt) {
                #pragma unroll
                for (int i = 0; i < 4; i++) s[i][j] = -1e30f;
            }
        }

        // ---------- online softmax (16-lane groups share 4 query rows) ----------
        float sc[4];
        #pragma unroll
        for (int i = 0; i < 4; i++) {
            float tm = fmaxf(fmaxf(s[i][0], s[i][1]), fmaxf(s[i][2], s[i][3]));
            #pragma unroll
            for (int off = 8; off >= 1; off >>= 1)
                tm = fmaxf(tm, __shfl_xor_sync(0xffffffffu, tm, off));
            float nm = fmaxf(m[i], tm);
            sc[i] = __expf(m[i] - nm);
            m[i]  = nm;
            float rs = 0.f;
            #pragma unroll
            for (int j = 0; j < 4; j++) {
                float p = __expf(s[i][j] - nm);
                s[i][j] = p;
                rs += p;
            }
            #pragma unroll
            for (int off = 8; off >= 1; off >>= 1)
                rs += __shfl_xor_sync(0xffffffffu, rs, off);
            l[i] = l[i] * sc[i] + rs;
        }
        #pragma unroll
        for (int i = 0; i < 4; i++)
            #pragma unroll
            for (int c2 = 0; c2 < 16; c2++) o[i * 16 + c2] *= sc[i];

        // store P tile [64][68]
        #pragma unroll
        for (int i = 0; i < 4; i++) {
            float4 pv = make_float4(s[i][0], s[i][1], s[i][2], s[i][3]);
            *(float4*)(Ps + ((ti << 2) + i) * 68 + (tj << 2)) = pv;
        }

        // ---------- GEMM2: O += P * F^T, dout chunks of 64 ----------
        #pragma unroll
        for (int c = 0; c < 4; c++) {
            #pragma unroll
            for (int i2 = 0; i2 < 4; i2++) {   // load F chunk [64][64] -> Fs[64][68]
                int fid = tid + (i2 << 8);
                int row = fid >> 4;
                int kq  = (fid & 15) << 2;
                float4 v = *(const float4*)(Fg + (size_t)(c * 64 + row) * NPIX + k0 + kq);
                *(float4*)(Fs + row * 68 + kq) = v;
            }
            __syncthreads();
            #pragma unroll 4
            for (int k4 = 0; k4 < 16; k4++) {
                float4 pv[4], fv[4];
                #pragma unroll
                for (int i = 0; i < 4; i++)
                    pv[i] = *(const float4*)(Ps + ((ti << 2) + i) * 68 + (k4 << 2));
                #pragma unroll
                for (int j = 0; j < 4; j++)
                    fv[j] = *(const float4*)(Fs + ((tj << 2) + j) * 68 + (k4 << 2));
                #pragma unroll
                for (int i = 0; i < 4; i++)
                    #pragma unroll
                    for (int j = 0; j < 4; j++)
                        o[i * 16 + (c << 2) + j] +=
                            pv[i].x * fv[j].x + pv[i].y * fv[j].y +
                            pv[i].z * fv[j].z + pv[i].w * fv[j].w;
            }
            __syncthreads();
        }
    }

    // ---------- epilogue: divide by l, stage, coalesced scatter ----------
    float rl[4];
    #pragma unroll
    for (int i = 0; i < 4; i++) rl[i] = 1.0f / l[i];

    float* ob = out + (size_t)b * 768 * NPIX + (size_t)512 * NPIX;
    float* Os = Fs;     // reuse [64][68]
    #pragma unroll
    for (int c = 0; c < 4; c++) {
        __syncthreads();
        #pragma unroll
        for (int i = 0; i < 4; i++)
            #pragma unroll
            for (int j = 0; j < 4; j++)
                Os[((tj << 2) + j) * 68 + (ti << 2) + i] = o[i * 16 + (c << 2) + j] * rl[i];
        __syncthreads();
        #pragma unroll
        for (int w = 0; w < 16; w++) {
            int row = (tid >> 6) + (w << 2);       // 0..63 (dout within chunk)
            int q   = tid & 63;
            int n   = qn[q];
            if (n >= 0)
                ob[(size_t)(c * 64 + row) * NPIX + n] = Os[row * 68 + q];
        }
    }
}

// ---------------- launch ------------------------------------------------------
extern "C" void kernel_launch(void* const* d_in, const int* in_sizes, int n_in,
                              void* d_out, int out_size)
{
    const float* x    = (const float*)d_in[0];
    const void*  mask = d_in[1];
    float*       out  = (float*)d_out;

    const int N = in_sizes[1];                  // 4096
    const int B = in_sizes[0] / (512 * N);      // 8

    k_compact<<<1, 128>>>(mask, N);
    k_pack<<<dim3(N / 32, B), 256>>>(x);
    {
        size_t totalF4 = (size_t)B * 768 * N / 4;
        int blocks = (int)(totalF4 / 256);
        k_out<<<blocks, 256>>>(x, out, N);
    }
    cudaFuncSetAttribute(k_attn, cudaFuncAttributeMaxDynamicSharedMemorySize, SM_BYTES);
    k_attn<<<dim3(N / 64, B), 256, SM_BYTES>>>(out);
}

// round 5
// speedup vs baseline: 2.5438x; 2.5438x over previous
#include <cuda_runtime.h>
#include <cstdint>
#include <cstddef>

// Fixed problem shapes: x: [B, 512, 64, 64] f32, mask: [64, 64] bool. d=256, N=4096.
#define BMAX   8
#define DDIM   256
#define NPIX   4096

// ---------------- scratch (device globals) ------------------------------------
__device__ float g_Q[(size_t)BMAX * DDIM * NPIX];   // normalized latter, hole cols, d-major [b][d][qpos]
__device__ float g_K[(size_t)BMAX * DDIM * NPIX];   // normalized latter, known cols, d-major [b][d][kpos]
__device__ float g_F[(size_t)BMAX * NPIX * DDIM];   // former, known cols, TRANSPOSED: [b][kpos][d]
__device__ int   g_qidx[NPIX];
__device__ int   g_pos [NPIX];
__device__ int   g_isq [NPIX];
__device__ int   g_cnt [2];                         // [0]=qcnt, [1]=kcnt

// ---------------- kernel 0: deterministic mask compaction ---------------------
__global__ void k_compact(const void* __restrict__ maskp, int N)
{
    __shared__ int cq[129];
    __shared__ int s_isu8;
    const int CH = N / 128;
    int t = threadIdx.x;

    if (t == 0) {
        const unsigned* w = (const unsigned*)maskp;
        int u8 = 0;
        for (int i = 0; i < N / 4; i++) { if (w[i] > 1u) { u8 = 1; break; } }
        s_isu8 = u8;
    }
    __syncthreads();
    const int isu8 = s_isu8;
    const unsigned char* mb = (const unsigned char*)maskp;
    const int*           mw = (const int*)maskp;

    int nq = 0;
    for (int i = t * CH; i < t * CH + CH; i++)
        nq += (isu8 ? (mb[i] != 0) : (mw[i] != 0));
    cq[t] = nq;
    __syncthreads();
    if (t == 0) {
        int acc = 0;
        for (int i = 0; i < 128; i++) { int v = cq[i]; cq[i] = acc; acc += v; }
        cq[128] = acc;
        g_cnt[0] = acc;
        g_cnt[1] = N - acc;
    }
    __syncthreads();
    int q = cq[t];
    int k = t * CH - cq[t];
    for (int i = t * CH; i < t * CH + CH; i++) {
        int f = (isu8 ? (mb[i] != 0) : (mw[i] != 0));
        if (f) { g_qidx[q] = i; g_pos[i] = q; g_isq[i] = 1; q++; }
        else   {               g_pos[i] = k; g_isq[i] = 0; k++; }
    }
}

// ---------------- kernel 1: column norms + compacted pack ---------------------
// grid (N/32, B), 256 threads. Phase A: norms + Q/K (d-major). Phase B: former
// transposed into g_F[b][kpos][d] for conflict-free attention loads.
__global__ void k_pack(const float* __restrict__ x)
{
    __shared__ float tile[256][33];
    __shared__ float psum[8][32];
    __shared__ float inv_s[32];
    __shared__ int   pp[32], mq[32];

    const int b  = blockIdx.y;
    const int n0 = blockIdx.x * 32;
    const int tx = threadIdx.x & 31;
    const int ty = threadIdx.x >> 5;       // 0..7

    const float* lat = x + ((size_t)b * 512 + 256) * NPIX;

    for (int r = ty; r < 256; r += 8)
        tile[r][tx] = lat[(size_t)r * NPIX + n0 + tx];
    if (threadIdx.x < 32) { pp[tx] = g_pos[n0 + tx]; mq[tx] = g_isq[n0 + tx]; }
    __syncthreads();

    float ss = 0.f;
    for (int r = ty * 32; r < ty * 32 + 32; r++) { float v = tile[r][tx]; ss += v * v; }
    psum[ty][tx] = ss;
    __syncthreads();
    if (threadIdx.x < 32) {
        float s = 0.f;
        #pragma unroll
        for (int i = 0; i < 8; i++) s += psum[i][tx];
        inv_s[tx] = 1.0f / (sqrtf(s) + 1e-8f);
    }
    __syncthreads();

    const float inv = inv_s[tx];
    const int   p   = pp[tx];
    const int   isq = mq[tx];
    float* dst = (isq ? g_Q : g_K) + (size_t)b * DDIM * NPIX + p;
    for (int r = ty; r < 256; r += 8)
        dst[(size_t)r * NPIX] = tile[r][tx] * inv;

    // ---- phase B: former, transposed to [kpos][d] ----
    __syncthreads();
    const float* fm = x + (size_t)b * 512 * NPIX;
    for (int r = ty; r < 256; r += 8)
        tile[r][tx] = fm[(size_t)r * NPIX + n0 + tx];
    __syncthreads();
    if (!isq) {
        float* df = g_F + ((size_t)b * NPIX + p) * DDIM;
        for (int r4 = ty * 4; r4 < 256; r4 += 32) {
            float4 v = make_float4(tile[r4][tx], tile[r4+1][tx],
                                   tile[r4+2][tx], tile[r4+3][tx]);
            *(float4*)(df + r4) = v;
        }
    }
}

// ---------------- kernel 2: copy former/latter, zero shift region -------------
__global__ void k_out(const float* __restrict__ x, float* __restrict__ out, int N)
{
    const size_t perB  = (size_t)768 * N / 4;
    const size_t copyB = (size_t)512 * N / 4;
    size_t f = (size_t)blockIdx.x * 256 + threadIdx.x;
    size_t b = f / perB;
    size_t r = f % perB;
    float4 v;
    if (r < copyB) v = ((const float4*)x)[b * copyB + r];
    else           v = make_float4(0.f, 0.f, 0.f, 0.f);
    ((float4*)out)[f] = v;
}

// ---------------- kernel 3: fused flash-attention -----------------------------
// grid (N/64, B), 256 threads. 64-query tiles, 64-key tiles.
// GEMM1: 32-d double-buffered K chunks, F-tile staging folded in (10 syncs/tile).
// GEMM2: single k-loop, 4q x 16dout register tile, conflict-free smem.
#define SM_QS   0                          // [256][64]     16384
#define SM_KS   16384                      // [2][32][64]    4096
#define SM_PS   20480                      // [64][68]       4352
#define SM_FT   24832                      // [64][260]     16640
#define SM_FLT  41472
#define SM_BYTES (SM_FLT * 4 + 64 * 4)     // 166144 B

__global__ void __launch_bounds__(256)
k_attn(float* __restrict__ out)
{
    extern __shared__ float sm[];
    float* Qs = sm + SM_QS;
    float* Ks = sm + SM_KS;
    float* Ps = sm + SM_PS;
    float* Ft = sm + SM_FT;
    int*   qn = (int*)(sm + SM_FLT);

    const int b    = blockIdx.y;
    const int qcnt = g_cnt[0];
    const int kcnt = g_cnt[1];
    const int q0   = blockIdx.x * 64;
    if (q0 >= qcnt) return;

    const int tid = threadIdx.x;
    const int ti  = tid >> 4;     // 0..15 -> 4 query rows
    const int tj  = tid & 15;     // 0..15 -> key cols / dout groups

    // ---- load Q tile into smem, d-major [dd][q], zero rows past qcnt ----
    {
        const float* Qg = g_Q + (size_t)b * DDIM * NPIX + q0;
        #pragma unroll
        for (int i = 0; i < 16; i++) {
            int fid = tid + i * 256;
            int dd  = fid >> 4;
            int qq  = (fid & 15) << 2;
            float4 v = *(const float4*)(Qg + (size_t)dd * NPIX + qq);
            int qb = q0 + qq;
            if (qb + 3 >= qcnt) {
                if (qb + 0 >= qcnt) v.x = 0.f;
                if (qb + 1 >= qcnt) v.y = 0.f;
                if (qb + 2 >= qcnt) v.z = 0.f;
                if (qb + 3 >= qcnt) v.w = 0.f;
            }
            *(float4*)(Qs + dd * 64 + qq) = v;
        }
        if (tid < 64) qn[tid] = (q0 + tid < qcnt) ? g_qidx[q0 + tid] : -1;
    }
    __syncthreads();

    float o[64];
    #pragma unroll
    for (int i = 0; i < 64; i++) o[i] = 0.f;
    float m[4], l[4];
    #pragma unroll
    for (int i = 0; i < 4; i++) { m[i] = -1e30f; l[i] = 0.f; }

    const float* Kg = g_K + (size_t)b * DDIM * NPIX;
    const float* Fg = g_F + (size_t)b * NPIX * DDIM;
    const int ntiles = (kcnt + 63) >> 6;

    // staging indices
    const int kdd = tid >> 4;            // K chunk: rows kdd, kdd+16
    const int kkq = (tid & 15) << 2;

    for (int kt = 0; kt < ntiles; kt++) {
        const int k0 = kt << 6;

        // ---- stage K chunk 0 into buffer 0 ----
        #pragma unroll
        for (int h = 0; h < 2; h++) {
            int dd = kdd + (h << 4);
            float4 v = *(const float4*)(Kg + (size_t)dd * NPIX + k0 + kkq);
            *(float4*)(Ks + dd * 64 + kkq) = v;
        }
        __syncthreads();

        // ---------- GEMM1: S = Q^T K, 8 chunks of 32 d, double-buffered ----------
        float s[4][4];
        #pragma unroll
        for (int i = 0; i < 4; i++)
            #pragma unroll
            for (int j = 0; j < 4; j++) s[i][j] = 0.f;

        #pragma unroll 1
        for (int dc = 0; dc < 8; dc++) {
            const int cur = dc & 1, nxt = cur ^ 1;
            // issue gmem loads for next K chunk + this chunk's F-tile slice
            float4 kn0, kn1;
            if (dc + 1 < 8) {
                int dbase = (dc + 1) * 32;
                kn0 = *(const float4*)(Kg + (size_t)(dbase + kdd)      * NPIX + k0 + kkq);
                kn1 = *(const float4*)(Kg + (size_t)(dbase + kdd + 16) * NPIX + k0 + kkq);
            }
            float4 fn0, fn1;
            int fid0 = tid + (dc * 2 + 0) * 256;
            int fid1 = tid + (dc * 2 + 1) * 256;
            int fk0 = fid0 >> 6, fd0 = (fid0 & 63) << 2;
            int fk1 = fid1 >> 6, fd1 = (fid1 & 63) << 2;
            fn0 = *(const float4*)(Fg + (size_t)(k0 + fk0) * DDIM + fd0);
            fn1 = *(const float4*)(Fg + (size_t)(k0 + fk1) * DDIM + fd1);

            // compute on current buffer
            const float* Kb = Ks + cur * 2048;
            #pragma unroll
            for (int dd = 0; dd < 32; dd++) {
                float4 qv = *(const float4*)(Qs + (dc * 32 + dd) * 64 + (ti << 2));
                float4 kv = *(const float4*)(Kb + dd * 64 + (tj << 2));
                float qa[4] = {qv.x, qv.y, qv.z, qv.w};
                float ka[4] = {kv.x, kv.y, kv.z, kv.w};
                #pragma unroll
                for (int i = 0; i < 4; i++)
                    #pragma unroll
                    for (int j = 0; j < 4; j++) s[i][j] += qa[i] * ka[j];
            }

            // commit staged data
            if (dc + 1 < 8) {
                *(float4*)(Ks + nxt * 2048 + kdd * 64 + kkq)        = kn0;
                *(float4*)(Ks + nxt * 2048 + (kdd + 16) * 64 + kkq) = kn1;
            }
            *(float4*)(Ft + fk0 * 260 + fd0) = fn0;
            *(float4*)(Ft + fk1 * 260 + fd1) = fn1;
            __syncthreads();
        }

        // mask out-of-range keys (last partial tile)
        #pragma unroll
        for (int j = 0; j < 4; j++) {
            if (k0 + (tj << 2) + j >= kcnt) {
                #pragma unroll
                for (int i = 0; i < 4; i++) s[i][j] = -1e30f;
            }
        }

        // ---------- online softmax (16-lane groups) ----------
        float sc[4];
        #pragma unroll
        for (int i = 0; i < 4; i++) {
            float tm = fmaxf(fmaxf(s[i][0], s[i][1]), fmaxf(s[i][2], s[i][3]));
            #pragma unroll
            for (int off = 8; off >= 1; off >>= 1)
                tm = fmaxf(tm, __shfl_xor_sync(0xffffffffu, tm, off));
            float nm = fmaxf(m[i], tm);
            sc[i] = __expf(m[i] - nm);
            m[i]  = nm;
            float rs = 0.f;
            #pragma unroll
            for (int j = 0; j < 4; j++) {
                float p = __expf(s[i][j] - nm);
                s[i][j] = p;
                rs += p;
            }
            #pragma unroll
            for (int off = 8; off >= 1; off >>= 1)
                rs += __shfl_xor_sync(0xffffffffu, rs, off);
            l[i] = l[i] * sc[i] + rs;
        }
        #pragma unroll
        for (int i = 0; i < 4; i++)
            #pragma unroll
            for (int c2 = 0; c2 < 16; c2++) o[i * 16 + c2] *= sc[i];

        // store P tile [64][68]
        #pragma unroll
        for (int i = 0; i < 4; i++)
            *(float4*)(Ps + ((ti << 2) + i) * 68 + (tj << 2)) =
                make_float4(s[i][0], s[i][1], s[i][2], s[i][3]);
        __syncthreads();

        // ---------- GEMM2: O[4q x 16dout] += P * Ft ----------
        #pragma unroll 2
        for (int k4 = 0; k4 < 16; k4++) {
            float pa[4][4];
            #pragma unroll
            for (int i = 0; i < 4; i++) {
                float4 t = *(const float4*)(Ps + ((ti << 2) + i) * 68 + (k4 << 2));
                pa[i][0] = t.x; pa[i][1] = t.y; pa[i][2] = t.z; pa[i][3] = t.w;
            }
            #pragma unroll
            for (int kk = 0; kk < 4; kk++) {
                const float* Fr = Ft + ((k4 << 2) + kk) * 260 + (tj << 2);
                #pragma unroll
                for (int c = 0; c < 4; c++) {
                    float4 fv = *(const float4*)(Fr + (c << 6));
                    #pragma unroll
                    for (int i = 0; i < 4; i++) {
                        float p = pa[i][kk];
                        o[i * 16 + (c << 2) + 0] += p * fv.x;
                        o[i * 16 + (c << 2) + 1] += p * fv.y;
                        o[i * 16 + (c << 2) + 2] += p * fv.z;
                        o[i * 16 + (c << 2) + 3] += p * fv.w;
                    }
                }
            }
        }
        __syncthreads();   // Ft/Ps reusable next tile
    }

    // ---------- epilogue: divide by l, stage in Ft[64q][260], scatter ----------
    float rl[4];
    #pragma unroll
    for (int i = 0; i < 4; i++) rl[i] = 1.0f / l[i];

    #pragma unroll
    for (int i = 0; i < 4; i++) {
        int q = (ti << 2) + i;
        #pragma unroll
        for (int c = 0; c < 4; c++) {
            float4 v = make_float4(o[i * 16 + (c << 2) + 0] * rl[i],
                                   o[i * 16 + (c << 2) + 1] * rl[i],
                                   o[i * 16 + (c << 2) + 2] * rl[i],
                                   o[i * 16 + (c << 2) + 3] * rl[i]);
            *(float4*)(Ft + q * 260 + (c << 6) + (tj << 2)) = v;
        }
    }
    __syncthreads();

    float* ob = out + (size_t)b * 768 * NPIX + (size_t)512 * NPIX;
    const int q  = tid & 63;
    const int n  = qn[q];
    if (n >= 0) {
        for (int r = tid >> 6; r < 256; r += 4)
            ob[(size_t)r * NPIX + n] = Ft[q * 260 + r];
    }
}

// ---------------- launch ------------------------------------------------------
extern "C" void kernel_launch(void* const* d_in, const int* in_sizes, int n_in,
                              void* d_out, int out_size)
{
    const float* x    = (const float*)d_in[0];
    const void*  mask = d_in[1];
    float*       out  = (float*)d_out;

    const int N = in_sizes[1];                  // 4096
    const int B = in_sizes[0] / (512 * N);      // 8

    k_compact<<<1, 128>>>(mask, N);
    k_pack<<<dim3(N / 32, B), 256>>>(x);
    {
        size_t totalF4 = (size_t)B * 768 * N / 4;
        int blocks = (int)(totalF4 / 256);
        k_out<<<blocks, 256>>>(x, out, N);
    }
    cudaFuncSetAttribute(k_attn, cudaFuncAttributeMaxDynamicSharedMemorySize, SM_BYTES);
    k_attn<<<dim3(N / 64, B), 256, SM_BYTES>>>(out);
}

// round 6
// speedup vs baseline: 11.2141x; 4.4085x over previous
#include <cuda_runtime.h>
#include <cuda_bf16.h>
#include <cstdint>
#include <cstddef>

// Fixed problem shapes: x: [B, 512, 64, 64] f32, mask: [64, 64] bool. d=256, N=4096.
#define BMAX   8
#define DDIM   256
#define NPIX   4096

// ---------------- scratch (device globals; zero-initialized) ------------------
__device__ __nv_bfloat16 g_Qh[(size_t)BMAX * NPIX * DDIM];  // normalized latter, hole rows [b][qpos][d]
__device__ __nv_bfloat16 g_Kh[(size_t)BMAX * NPIX * DDIM];  // normalized latter, known rows [b][kpos][d]
__device__ __nv_bfloat16 g_Fh[(size_t)BMAX * NPIX * DDIM];  // former, known rows [b][kpos][d]
__device__ int   g_qidx[NPIX];
__device__ int   g_pos [NPIX];
__device__ int   g_isq [NPIX];
__device__ int   g_cnt [2];                                 // [0]=qcnt, [1]=kcnt

// ---------------- ptx helpers --------------------------------------------------
__device__ __forceinline__ uint32_t smem_u32(const void* p) {
    uint32_t a;
    asm("{ .reg .u64 t; cvta.to.shared.u64 t, %1; cvt.u32.u64 %0, t; }" : "=r"(a) : "l"(p));
    return a;
}
__device__ __forceinline__ void ldsm4(uint32_t& r0, uint32_t& r1, uint32_t& r2, uint32_t& r3, uint32_t a) {
    asm volatile("ldmatrix.sync.aligned.m8n8.x4.shared.b16 {%0,%1,%2,%3}, [%4];"
                 : "=r"(r0), "=r"(r1), "=r"(r2), "=r"(r3) : "r"(a));
}
__device__ __forceinline__ void ldsm4t(uint32_t& r0, uint32_t& r1, uint32_t& r2, uint32_t& r3, uint32_t a) {
    asm volatile("ldmatrix.sync.aligned.m8n8.x4.trans.shared.b16 {%0,%1,%2,%3}, [%4];"
                 : "=r"(r0), "=r"(r1), "=r"(r2), "=r"(r3) : "r"(a));
}
__device__ __forceinline__ void mma16816(float* c, uint32_t a0, uint32_t a1, uint32_t a2, uint32_t a3,
                                         uint32_t b0, uint32_t b1) {
    asm volatile("mma.sync.aligned.m16n8k16.row.col.f32.bf16.bf16.f32 "
                 "{%0,%1,%2,%3}, {%4,%5,%6,%7}, {%8,%9}, {%0,%1,%2,%3};"
                 : "+f"(c[0]), "+f"(c[1]), "+f"(c[2]), "+f"(c[3])
                 : "r"(a0), "r"(a1), "r"(a2), "r"(a3), "r"(b0), "r"(b1));
}
__device__ __forceinline__ uint32_t pack_bf2(float lo, float hi) {
    __nv_bfloat162 h = __floats2bfloat162_rn(lo, hi);
    return *(uint32_t*)&h;
}

// ---------------- kernel 0: deterministic mask compaction ---------------------
__global__ void k_compact(const void* __restrict__ maskp, int N)
{
    __shared__ int cq[129];
    __shared__ int s_isu8;
    const int CH = N / 128;
    int t = threadIdx.x;

    if (t == 0) {
        const unsigned* w = (const unsigned*)maskp;
        int u8 = 0;
        for (int i = 0; i < N / 4; i++) { if (w[i] > 1u) { u8 = 1; break; } }
        s_isu8 = u8;
    }
    __syncthreads();
    const int isu8 = s_isu8;
    const unsigned char* mb = (const unsigned char*)maskp;
    const int*           mw = (const int*)maskp;

    int nq = 0;
    for (int i = t * CH; i < t * CH + CH; i++)
        nq += (isu8 ? (mb[i] != 0) : (mw[i] != 0));
    cq[t] = nq;
    __syncthreads();
    if (t == 0) {
        int acc = 0;
        for (int i = 0; i < 128; i++) { int v = cq[i]; cq[i] = acc; acc += v; }
        cq[128] = acc;
        g_cnt[0] = acc;
        g_cnt[1] = N - acc;
    }
    __syncthreads();
    int q = cq[t];
    int k = t * CH - cq[t];
    for (int i = t * CH; i < t * CH + CH; i++) {
        int f = (isu8 ? (mb[i] != 0) : (mw[i] != 0));
        if (f) { g_qidx[q] = i; g_pos[i] = q; g_isq[i] = 1; q++; }
        else   {               g_pos[i] = k; g_isq[i] = 0; k++; }
    }
}

// ---------------- kernel 1: column norms + compacted bf16 pack -----------------
// grid (N/32, B), 256 threads. Row-major bf16 outputs [pos][256].
__global__ void k_pack(const float* __restrict__ x)
{
    __shared__ float tile[256][33];
    __shared__ float psum[8][32];
    __shared__ float inv_s[32];
    __shared__ int   pp[32], mq[32];

    const int b  = blockIdx.y;
    const int n0 = blockIdx.x * 32;
    const int tx = threadIdx.x & 31;
    const int ty = threadIdx.x >> 5;

    const float* lat = x + ((size_t)b * 512 + 256) * NPIX;
    for (int r = ty; r < 256; r += 8)
        tile[r][tx] = lat[(size_t)r * NPIX + n0 + tx];
    if (threadIdx.x < 32) { pp[tx] = g_pos[n0 + tx]; mq[tx] = g_isq[n0 + tx]; }
    __syncthreads();

    float ss = 0.f;
    for (int r = ty * 32; r < ty * 32 + 32; r++) { float v = tile[r][tx]; ss += v * v; }
    psum[ty][tx] = ss;
    __syncthreads();
    if (threadIdx.x < 32) {
        float s = 0.f;
        #pragma unroll
        for (int i = 0; i < 8; i++) s += psum[i][tx];
        inv_s[tx] = 1.0f / (sqrtf(s) + 1e-8f);
    }
    __syncthreads();

    const float inv = inv_s[tx];
    const int   p   = pp[tx];
    const int   isq = mq[tx];
    {
        __nv_bfloat16* dst = (isq ? g_Qh : g_Kh) + ((size_t)b * NPIX + p) * DDIM;
        #pragma unroll
        for (int i = 0; i < 4; i++) {
            int r8 = ty * 8 + i * 64;
            uint32_t w0 = pack_bf2(tile[r8+0][tx]*inv, tile[r8+1][tx]*inv);
            uint32_t w1 = pack_bf2(tile[r8+2][tx]*inv, tile[r8+3][tx]*inv);
            uint32_t w2 = pack_bf2(tile[r8+4][tx]*inv, tile[r8+5][tx]*inv);
            uint32_t w3 = pack_bf2(tile[r8+6][tx]*inv, tile[r8+7][tx]*inv);
            *(uint4*)(dst + r8) = make_uint4(w0, w1, w2, w3);
        }
    }

    // ---- phase B: former -> g_Fh[kpos][d] ----
    __syncthreads();
    const float* fm = x + (size_t)b * 512 * NPIX;
    for (int r = ty; r < 256; r += 8)
        tile[r][tx] = fm[(size_t)r * NPIX + n0 + tx];
    __syncthreads();
    if (!isq) {
        __nv_bfloat16* df = g_Fh + ((size_t)b * NPIX + p) * DDIM;
        #pragma unroll
        for (int i = 0; i < 4; i++) {
            int r8 = ty * 8 + i * 64;
            uint32_t w0 = pack_bf2(tile[r8+0][tx], tile[r8+1][tx]);
            uint32_t w1 = pack_bf2(tile[r8+2][tx], tile[r8+3][tx]);
            uint32_t w2 = pack_bf2(tile[r8+4][tx], tile[r8+5][tx]);
            uint32_t w3 = pack_bf2(tile[r8+6][tx], tile[r8+7][tx]);
            *(uint4*)(df + r8) = make_uint4(w0, w1, w2, w3);
        }
    }
}

// ---------------- kernel 2: copy former/latter, zero shift region -------------
__global__ void k_out(const float* __restrict__ x, float* __restrict__ out, int N)
{
    const size_t perB  = (size_t)768 * N / 4;
    const size_t copyB = (size_t)512 * N / 4;
    size_t f = (size_t)blockIdx.x * 256 + threadIdx.x;
    size_t b = f / perB;
    size_t r = f % perB;
    float4 v;
    if (r < copyB) v = ((const float4*)x)[b * copyB + r];
    else           v = make_float4(0.f, 0.f, 0.f, 0.f);
    ((float4*)out)[f] = v;
}

// ---------------- kernel 3: bf16 tensor-core flash attention -------------------
// 256 threads = 2 groups x 4 warps. Group g handles key tiles g, g+2, ...
// independent online softmax; merged at the end through smem.
#define QOFF    0
#define QN_OFF  32768
#define ML_M    33024
#define ML_L    33280
#define KOFF0   33792
#define FOFF0   99328
#define O1OFF   33792          /* reuse after mainloop */
#define OBOFF   101888
#define OSTRIDE 266
#define SMB     169984

#define STAGE_TILE(SRC, DSTB, K0)                                               \
    do {                                                                        \
        _Pragma("unroll")                                                       \
        for (int _i = 0; _i < 16; _i++) {                                       \
            int _idx = tg + _i * 128;                                           \
            int _row = _idx >> 5, _ch = _idx & 31;                              \
            const __nv_bfloat16* _gp = (SRC) + ((size_t)((K0) + _row) * DDIM + _ch * 8); \
            uint32_t _sa = (DSTB) + _row * 512 + ((_ch ^ (_row & 7)) << 4);     \
            asm volatile("cp.async.cg.shared.global [%0], [%1], 16;"            \
                         :: "r"(_sa), "l"(_gp) : "memory");                     \
        }                                                                       \
        asm volatile("cp.async.commit_group;" ::: "memory");                    \
    } while (0)

__global__ void __launch_bounds__(256, 1)
k_attn(float* __restrict__ out)
{
    extern __shared__ char sm[];
    const uint32_t sb = smem_u32(sm);

    const int b    = blockIdx.y;
    const int qcnt = g_cnt[0];
    const int kcnt = g_cnt[1];
    const int q0   = blockIdx.x * 64;
    if (q0 >= qcnt) return;

    const int tid  = threadIdx.x;
    const int lane = tid & 31;
    const int warp = tid >> 5;
    const int g    = warp >> 2;     // key group
    const int mw   = warp & 3;      // query 16-row slab
    const int tg   = tid & 127;

    // ---- stage Q tile (swizzled bf16 [64][256]), zero rows past qcnt ----
    {
        const __nv_bfloat16* Qg = g_Qh + (size_t)b * NPIX * DDIM;
        #pragma unroll
        for (int i = 0; i < 8; i++) {
            int idx = tid + i * 256;
            int row = idx >> 5, ch = idx & 31;
            uint4 v = make_uint4(0u, 0u, 0u, 0u);
            if (q0 + row < qcnt)
                v = *(const uint4*)(Qg + ((size_t)(q0 + row) * DDIM + ch * 8));
            *(uint4*)(sm + QOFF + row * 512 + ((ch ^ (row & 7)) << 4)) = v;
        }
        if (tid < 64) ((int*)(sm + QN_OFF))[tid] = (q0 + tid < qcnt) ? g_qidx[q0 + tid] : -1;
    }
    __syncthreads();

    const __nv_bfloat16* Kg = g_Kh + (size_t)b * NPIX * DDIM;
    const __nv_bfloat16* Fg = g_Fh + (size_t)b * NPIX * DDIM;
    const int ntt = (kcnt + 63) >> 6;
    const int ntg = (g == 0) ? ((ntt + 1) >> 1) : (ntt >> 1);

    // per-lane fragment address constants
    const int aRow      = mw * 16 + (lane & 15);
    const uint32_t aB   = sb + QOFF + aRow * 512;
    const int aSw       = aRow & 7;
    const int aCb       = lane >> 4;
    const int bRowOff   = (lane & 7) + ((lane >> 4) << 3);
    const int bCb       = (lane >> 3) & 1;
    const int fRowOff   = (lane & 7) + (((lane >> 3) & 1) << 3);
    const int fCb       = (lane >> 4) & 1;
    const uint32_t Kbase = sb + KOFF0 + g * 32768;
    const uint32_t Fbase = sb + FOFF0 + g * 32768;
    const int barid = 1 + g;

    float o[32][4];
    #pragma unroll
    for (int j = 0; j < 32; j++) { o[j][0] = o[j][1] = o[j][2] = o[j][3] = 0.f; }
    float m0v = -1e30f, m1v = -1e30f, l0v = 0.f, l1v = 0.f;

    if (ntg > 0) { STAGE_TILE(Kg, Kbase, g * 64); STAGE_TILE(Fg, Fbase, g * 64); }

    for (int t = 0; t < ntg; t++) {
        const int k0 = (g + 2 * t) * 64;

        asm volatile("cp.async.wait_group 1;" ::: "memory");     // K ready
        asm volatile("bar.sync %0, 128;" :: "r"(barid) : "memory");

        // ---------- GEMM1: S[16q x 64k] = Q K^T ----------
        float s[8][4];
        #pragma unroll
        for (int j = 0; j < 8; j++) { s[j][0] = s[j][1] = s[j][2] = s[j][3] = 0.f; }

        #pragma unroll
        for (int ks = 0; ks < 16; ks++) {
            uint32_t a0, a1, a2, a3;
            ldsm4(a0, a1, a2, a3, aB + (((2 * ks + aCb) ^ aSw) << 4));
            #pragma unroll
            for (int p = 0; p < 4; p++) {
                int row = 16 * p + bRowOff;
                uint32_t r0, r1, r2, r3;
                ldsm4(r0, r1, r2, r3, Kbase + row * 512 + (((2 * ks + bCb) ^ (row & 7)) << 4));
                mma16816(s[2 * p],     a0, a1, a2, a3, r0, r1);
                mma16816(s[2 * p + 1], a0, a1, a2, a3, r2, r3);
            }
        }

        // mask out-of-range key columns (generic tail)
        if (k0 + 64 > kcnt) {
            #pragma unroll
            for (int j = 0; j < 8; j++) {
                int n0 = k0 + 8 * j + 2 * (lane & 3);
                if (n0     >= kcnt) { s[j][0] = -1e30f; s[j][2] = -1e30f; }
                if (n0 + 1 >= kcnt) { s[j][1] = -1e30f; s[j][3] = -1e30f; }
            }
        }

        asm volatile("bar.sync %0, 128;" :: "r"(barid) : "memory"); // done reading K
        if (t + 1 < ntg) STAGE_TILE(Kg, Kbase, (g + 2 * (t + 1)) * 64);

        // ---------- online softmax (quad reduce: rows shared by lanes of a quad) ----------
        float tm0 = -1e30f, tm1 = -1e30f;
        #pragma unroll
        for (int j = 0; j < 8; j++) {
            tm0 = fmaxf(tm0, fmaxf(s[j][0], s[j][1]));
            tm1 = fmaxf(tm1, fmaxf(s[j][2], s[j][3]));
        }
        #pragma unroll
        for (int off = 1; off <= 2; off <<= 1) {
            tm0 = fmaxf(tm0, __shfl_xor_sync(0xffffffffu, tm0, off));
            tm1 = fmaxf(tm1, __shfl_xor_sync(0xffffffffu, tm1, off));
        }
        float nm0 = fmaxf(m0v, tm0), nm1 = fmaxf(m1v, tm1);
        float sc0 = __expf(m0v - nm0), sc1 = __expf(m1v - nm1);
        m0v = nm0; m1v = nm1;
        float rs0 = 0.f, rs1 = 0.f;
        #pragma unroll
        for (int j = 0; j < 8; j++) {
            s[j][0] = __expf(s[j][0] - nm0);
            s[j][1] = __expf(s[j][1] - nm0);
            s[j][2] = __expf(s[j][2] - nm1);
            s[j][3] = __expf(s[j][3] - nm1);
            rs0 += s[j][0] + s[j][1];
            rs1 += s[j][2] + s[j][3];
        }
        #pragma unroll
        for (int off = 1; off <= 2; off <<= 1) {
            rs0 += __shfl_xor_sync(0xffffffffu, rs0, off);
            rs1 += __shfl_xor_sync(0xffffffffu, rs1, off);
        }
        l0v = l0v * sc0 + rs0;
        l1v = l1v * sc1 + rs1;
        #pragma unroll
        for (int j = 0; j < 32; j++) {
            o[j][0] *= sc0; o[j][1] *= sc0; o[j][2] *= sc1; o[j][3] *= sc1;
        }

        // P -> A fragments (accumulator layout == A-operand layout identity)
        uint32_t aP[4][4];
        #pragma unroll
        for (int kk = 0; kk < 4; kk++) {
            aP[kk][0] = pack_bf2(s[2*kk][0],   s[2*kk][1]);
            aP[kk][1] = pack_bf2(s[2*kk][2],   s[2*kk][3]);
            aP[kk][2] = pack_bf2(s[2*kk+1][0], s[2*kk+1][1]);
            aP[kk][3] = pack_bf2(s[2*kk+1][2], s[2*kk+1][3]);
        }

        // F ready?
        if (t + 1 < ntg) asm volatile("cp.async.wait_group 1;" ::: "memory");
        else             asm volatile("cp.async.wait_group 0;" ::: "memory");
        asm volatile("bar.sync %0, 128;" :: "r"(barid) : "memory");

        // ---------- GEMM2: O[16q x 256d] += P F ----------
        #pragma unroll
        for (int kk = 0; kk < 4; kk++) {
            #pragma unroll
            for (int p = 0; p < 16; p++) {
                int row = 16 * kk + fRowOff;
                uint32_t r0, r1, r2, r3;
                ldsm4t(r0, r1, r2, r3, Fbase + row * 512 + (((2 * p + fCb) ^ (row & 7)) << 4));
                mma16816(o[2 * p],     aP[kk][0], aP[kk][1], aP[kk][2], aP[kk][3], r0, r1);
                mma16816(o[2 * p + 1], aP[kk][0], aP[kk][1], aP[kk][2], aP[kk][3], r2, r3);
            }
        }

        asm volatile("bar.sync %0, 128;" :: "r"(barid) : "memory"); // done reading F
        if (t + 1 < ntg) STAGE_TILE(Fg, Fbase, (g + 2 * (t + 1)) * 64);
    }

    // ---------- merge the two key-groups ----------
    const int r0g = mw * 16 + (lane >> 2);
    const int col = 2 * (lane & 3);
    if (g == 1) {
        if ((lane & 3) == 0) {
            ((float*)(sm + ML_M))[r0g]     = m0v;
            ((float*)(sm + ML_M))[r0g + 8] = m1v;
            ((float*)(sm + ML_L))[r0g]     = l0v;
            ((float*)(sm + ML_L))[r0g + 8] = l1v;
        }
        float* O1 = (float*)(sm + O1OFF);
        #pragma unroll
        for (int j = 0; j < 32; j++) {
            *(float2*)(O1 + r0g * OSTRIDE + 8 * j + col)       = make_float2(o[j][0], o[j][1]);
            *(float2*)(O1 + (r0g + 8) * OSTRIDE + 8 * j + col) = make_float2(o[j][2], o[j][3]);
        }
    }
    __syncthreads();
    if (g == 0) {
        float mm0 = ((float*)(sm + ML_M))[r0g],     ll0 = ((float*)(sm + ML_L))[r0g];
        float mm1 = ((float*)(sm + ML_M))[r0g + 8], ll1 = ((float*)(sm + ML_L))[r0g + 8];
        float M0 = fmaxf(m0v, mm0), M1 = fmaxf(m1v, mm1);
        float e00 = __expf(m0v - M0), e01 = __expf(mm0 - M0);
        float e10 = __expf(m1v - M1), e11 = __expf(mm1 - M1);
        float i0 = 1.f / (e00 * l0v + e01 * ll0);
        float i1 = 1.f / (e10 * l1v + e11 * ll1);
        const float* O1 = (const float*)(sm + O1OFF);
        float* Ob = (float*)(sm + OBOFF);
        #pragma unroll
        for (int j = 0; j < 32; j++) {
            float2 x0 = *(const float2*)(O1 + r0g * OSTRIDE + 8 * j + col);
            float2 x1 = *(const float2*)(O1 + (r0g + 8) * OSTRIDE + 8 * j + col);
            *(float2*)(Ob + r0g * OSTRIDE + 8 * j + col) =
                make_float2((e00 * o[j][0] + e01 * x0.x) * i0,
                            (e00 * o[j][1] + e01 * x0.y) * i0);
            *(float2*)(Ob + (r0g + 8) * OSTRIDE + 8 * j + col) =
                make_float2((e10 * o[j][2] + e11 * x1.x) * i1,
                            (e10 * o[j][3] + e11 * x1.y) * i1);
        }
    }
    __syncthreads();

    // ---------- coalesced scatter into hole columns ----------
    {
        const int q = tid & 63;
        const int n = ((const int*)(sm + QN_OFF))[q];
        const float* Ob = (const float*)(sm + OBOFF);
        float* ob = out + ((size_t)b * 768 + 512) * NPIX;
        if (n >= 0) {
            for (int r = tid >> 6; r < 256; r += 4)
                ob[(size_t)r * NPIX + n] = Ob[q * OSTRIDE + r];
        }
    }
}

// ---------------- launch ------------------------------------------------------
extern "C" void kernel_launch(void* const* d_in, const int* in_sizes, int n_in,
                              void* d_out, int out_size)
{
    const float* x    = (const float*)d_in[0];
    const void*  mask = d_in[1];
    float*       out  = (float*)d_out;

    const int N = in_sizes[1];                  // 4096
    const int B = in_sizes[0] / (512 * N);      // 8

    k_compact<<<1, 128>>>(mask, N);
    k_pack<<<dim3(N / 32, B), 256>>>(x);
    {
        size_t totalF4 = (size_t)B * 768 * N / 4;
        int blocks = (int)(totalF4 / 256);
        k_out<<<blocks, 256>>>(x, out, N);
    }
    cudaFuncSetAttribute(k_attn, cudaFuncAttributeMaxDynamicSharedMemorySize, SMB);
    k_attn<<<dim3(N / 64, B), 256, SMB>>>(out);
}

// round 7
// speedup vs baseline: 12.0216x; 1.0720x over previous
#include <cuda_runtime.h>
#include <cuda_bf16.h>
#include <cstdint>
#include <cstddef>

// Fixed problem shapes: x: [B, 512, 64, 64] f32, mask: [64, 64] bool. d=256, N=4096.
#define BMAX   8
#define DDIM   256
#define NPIX   4096

// ---------------- scratch (device globals) ------------------------------------
__device__ __nv_bfloat16 g_Qh[(size_t)BMAX * NPIX * DDIM];  // normalized latter, hole rows [b][qpos][d]
__device__ __nv_bfloat16 g_Kh[(size_t)BMAX * NPIX * DDIM];  // normalized latter, known rows [b][kpos][d]
__device__ __nv_bfloat16 g_Fh[(size_t)BMAX * NPIX * DDIM];  // former, known rows [b][kpos][d]
__device__ int   g_qidx[NPIX];
__device__ int   g_pos [NPIX];
__device__ int   g_isq [NPIX];
__device__ int   g_cnt [2];                                 // [0]=qcnt, [1]=kcnt

// ---------------- ptx helpers --------------------------------------------------
__device__ __forceinline__ uint32_t smem_u32(const void* p) {
    uint32_t a;
    asm("{ .reg .u64 t; cvta.to.shared.u64 t, %1; cvt.u32.u64 %0, t; }" : "=r"(a) : "l"(p));
    return a;
}
__device__ __forceinline__ void ldsm4(uint32_t& r0, uint32_t& r1, uint32_t& r2, uint32_t& r3, uint32_t a) {
    asm volatile("ldmatrix.sync.aligned.m8n8.x4.shared.b16 {%0,%1,%2,%3}, [%4];"
                 : "=r"(r0), "=r"(r1), "=r"(r2), "=r"(r3) : "r"(a));
}
__device__ __forceinline__ void ldsm4t(uint32_t& r0, uint32_t& r1, uint32_t& r2, uint32_t& r3, uint32_t a) {
    asm volatile("ldmatrix.sync.aligned.m8n8.x4.trans.shared.b16 {%0,%1,%2,%3}, [%4];"
                 : "=r"(r0), "=r"(r1), "=r"(r2), "=r"(r3) : "r"(a));
}
__device__ __forceinline__ void mma16816(float* c, uint32_t a0, uint32_t a1, uint32_t a2, uint32_t a3,
                                         uint32_t b0, uint32_t b1) {
    asm volatile("mma.sync.aligned.m16n8k16.row.col.f32.bf16.bf16.f32 "
                 "{%0,%1,%2,%3}, {%4,%5,%6,%7}, {%8,%9}, {%0,%1,%2,%3};"
                 : "+f"(c[0]), "+f"(c[1]), "+f"(c[2]), "+f"(c[3])
                 : "r"(a0), "r"(a1), "r"(a2), "r"(a3), "r"(b0), "r"(b1));
}
__device__ __forceinline__ uint32_t pack_bf2(float lo, float hi) {
    __nv_bfloat162 h = __floats2bfloat162_rn(lo, hi);
    return *(uint32_t*)&h;
}

// ---------------- kernel 0: deterministic mask compaction ---------------------
__global__ void k_compact(const void* __restrict__ maskp, int N)
{
    __shared__ int cq[129];
    __shared__ int s_isu8;
    const int CH = N / 128;
    int t = threadIdx.x;

    if (t == 0) {
        const unsigned* w = (const unsigned*)maskp;
        int u8 = 0;
        for (int i = 0; i < N / 4; i++) { if (w[i] > 1u) { u8 = 1; break; } }
        s_isu8 = u8;
    }
    __syncthreads();
    const int isu8 = s_isu8;
    const unsigned char* mb = (const unsigned char*)maskp;
    const int*           mw = (const int*)maskp;

    int nq = 0;
    for (int i = t * CH; i < t * CH + CH; i++)
        nq += (isu8 ? (mb[i] != 0) : (mw[i] != 0));
    cq[t] = nq;
    __syncthreads();
    if (t == 0) {
        int acc = 0;
        for (int i = 0; i < 128; i++) { int v = cq[i]; cq[i] = acc; acc += v; }
        cq[128] = acc;
        g_cnt[0] = acc;
        g_cnt[1] = N - acc;
    }
    __syncthreads();
    int q = cq[t];
    int k = t * CH - cq[t];
    for (int i = t * CH; i < t * CH + CH; i++) {
        int f = (isu8 ? (mb[i] != 0) : (mw[i] != 0));
        if (f) { g_qidx[q] = i; g_pos[i] = q; g_isq[i] = 1; q++; }
        else   {               g_pos[i] = k; g_isq[i] = 0; k++; }
    }
}

// ---------------- kernel 1: fused prep ----------------------------------------
// grid (N/32, B), 256 threads. Single pass over x:
//   - copies former+latter into out channels [0,512)
//   - zero-fills out channels [512,768)
//   - computes column norms of latter, packs bf16 Q/K (compacted, row-major)
//   - packs bf16 F (compacted, row-major)
__global__ void k_prep(const float* __restrict__ x, float* __restrict__ out)
{
    __shared__ float tile[256][33];
    __shared__ float psum[8][32];
    __shared__ float inv_s[32];
    __shared__ int   pp[32], mq[32];

    const int b  = blockIdx.y;
    const int n0 = blockIdx.x * 32;
    const int tx = threadIdx.x & 31;
    const int ty = threadIdx.x >> 5;

    const float* lat = x + ((size_t)b * 512 + 256) * NPIX;
    float* outb = out + (size_t)b * 768 * NPIX;

    // phase 1: latter -> smem + copy out + zero shift rows
    for (int r = ty; r < 256; r += 8) {
        float v = lat[(size_t)r * NPIX + n0 + tx];
        tile[r][tx] = v;
        outb[(size_t)(256 + r) * NPIX + n0 + tx] = v;
        outb[(size_t)(512 + r) * NPIX + n0 + tx] = 0.f;
    }
    if (threadIdx.x < 32) { pp[tx] = g_pos[n0 + tx]; mq[tx] = g_isq[n0 + tx]; }
    __syncthreads();

    float ss = 0.f;
    for (int r = ty * 32; r < ty * 32 + 32; r++) { float v = tile[r][tx]; ss += v * v; }
    psum[ty][tx] = ss;
    __syncthreads();
    if (threadIdx.x < 32) {
        float s = 0.f;
        #pragma unroll
        for (int i = 0; i < 8; i++) s += psum[i][tx];
        inv_s[tx] = 1.0f / (sqrtf(s) + 1e-8f);
    }
    __syncthreads();

    const float inv = inv_s[tx];
    const int   p   = pp[tx];
    const int   isq = mq[tx];
    {
        __nv_bfloat16* dst = (isq ? g_Qh : g_Kh) + ((size_t)b * NPIX + p) * DDIM;
        #pragma unroll
        for (int i = 0; i < 4; i++) {
            int r8 = ty * 8 + i * 64;
            uint32_t w0 = pack_bf2(tile[r8+0][tx]*inv, tile[r8+1][tx]*inv);
            uint32_t w1 = pack_bf2(tile[r8+2][tx]*inv, tile[r8+3][tx]*inv);
            uint32_t w2 = pack_bf2(tile[r8+4][tx]*inv, tile[r8+5][tx]*inv);
            uint32_t w3 = pack_bf2(tile[r8+6][tx]*inv, tile[r8+7][tx]*inv);
            *(uint4*)(dst + r8) = make_uint4(w0, w1, w2, w3);
        }
    }

    // phase 2: former -> smem + copy out + pack F
    __syncthreads();
    const float* fm = x + (size_t)b * 512 * NPIX;
    for (int r = ty; r < 256; r += 8) {
        float v = fm[(size_t)r * NPIX + n0 + tx];
        tile[r][tx] = v;
        outb[(size_t)r * NPIX + n0 + tx] = v;
    }
    __syncthreads();
    if (!isq) {
        __nv_bfloat16* df = g_Fh + ((size_t)b * NPIX + p) * DDIM;
        #pragma unroll
        for (int i = 0; i < 4; i++) {
            int r8 = ty * 8 + i * 64;
            uint32_t w0 = pack_bf2(tile[r8+0][tx], tile[r8+1][tx]);
            uint32_t w1 = pack_bf2(tile[r8+2][tx], tile[r8+3][tx]);
            uint32_t w2 = pack_bf2(tile[r8+4][tx], tile[r8+5][tx]);
            uint32_t w3 = pack_bf2(tile[r8+6][tx], tile[r8+7][tx]);
            *(uint4*)(df + r8) = make_uint4(w0, w1, w2, w3);
        }
    }
}

// ---------------- kernel 2: bf16 tensor-core attention (no online max) --------
// 256 threads = 2 groups x 4 warps; group g handles key tiles g, g+2, ...
// Scores are cosines (<=1) -> exp(s) directly, no running max, no rescale.
// GEMM1: 2x2 warp layout (32q x 32k per warp). P staged through smem (bf16).
// GEMM2: d-split across the 4 warps (each warp owns 64 d channels; F read 1x).
// Merge: l via shared atomicAdd; O via smem sum; scale once; scatter.
#define QOFF    0                      // bf16 [64][256] swizzled      32768
#define QN_OFF  32768                  // int[64]                        256
#define SL_OFF  33024                  // float[64] l accumulators       256
#define KOFF    33280                  // bf16 K tiles, per group 32768
#define FOFF    98816                  // bf16 F tiles, per group 32768
#define POFF    164352                 // bf16 P [64][64] per group 8192
#define OB_OFF  33280                  // f32 [64][258] (reuses K/F region)
#define OSTRIDE 258
#define SMB     180736

#define STAGE_TILE(SRC, DSTB, K0)                                               \
    do {                                                                        \
        _Pragma("unroll")                                                       \
        for (int _i = 0; _i < 16; _i++) {                                       \
            int _idx = tg + _i * 128;                                           \
            int _row = _idx >> 5, _ch = _idx & 31;                              \
            const __nv_bfloat16* _gp = (SRC) + ((size_t)((K0) + _row) * DDIM + _ch * 8); \
            uint32_t _sa = (DSTB) + _row * 512 + ((_ch ^ (_row & 7)) << 4);     \
            asm volatile("cp.async.cg.shared.global [%0], [%1], 16;"            \
                         :: "r"(_sa), "l"(_gp) : "memory");                     \
        }                                                                       \
        asm volatile("cp.async.commit_group;" ::: "memory");                    \
    } while (0)

__global__ void __launch_bounds__(256, 1)
k_attn(float* __restrict__ out)
{
    extern __shared__ char sm[];
    const uint32_t sb = smem_u32(sm);

    const int b    = blockIdx.y;
    const int qcnt = g_cnt[0];
    const int kcnt = g_cnt[1];
    const int q0   = blockIdx.x * 64;
    if (q0 >= qcnt) return;

    const int tid  = threadIdx.x;
    const int lane = tid & 31;
    const int warp = tid >> 5;
    const int g    = warp >> 2;     // key group 0/1
    const int wg   = warp & 3;      // warp within group
    const int qh   = wg & 1;        // GEMM1: query half (32 rows)
    const int kh   = wg >> 1;       // GEMM1: key half (32 cols)
    const int tg   = tid & 127;

    // ---- stage Q tile (swizzled bf16 [64][256]); zero l accumulators ----
    {
        const __nv_bfloat16* Qg = g_Qh + (size_t)b * NPIX * DDIM;
        #pragma unroll
        for (int i = 0; i < 8; i++) {
            int idx = tid + i * 256;
            int row = idx >> 5, ch = idx & 31;
            uint4 v = make_uint4(0u, 0u, 0u, 0u);
            if (q0 + row < qcnt)
                v = *(const uint4*)(Qg + ((size_t)(q0 + row) * DDIM + ch * 8));
            *(uint4*)(sm + QOFF + row * 512 + ((ch ^ (row & 7)) << 4)) = v;
        }
        if (tid < 64) {
            ((int*)(sm + QN_OFF))[tid] = (q0 + tid < qcnt) ? g_qidx[q0 + tid] : -1;
            ((float*)(sm + SL_OFF))[tid] = 0.f;
        }
    }
    __syncthreads();

    const __nv_bfloat16* Kg = g_Kh + (size_t)b * NPIX * DDIM;
    const __nv_bfloat16* Fg = g_Fh + (size_t)b * NPIX * DDIM;
    const int ntt = (kcnt + 63) >> 6;
    const int ntg = (g == 0) ? ((ntt + 1) >> 1) : (ntt >> 1);

    const uint32_t Kbase = sb + KOFF + g * 32768;
    const uint32_t Fbase = sb + FOFF + g * 32768;
    const uint32_t Pbase = sb + POFF + g * 8192;
    const int barid = 1 + g;

    // GEMM1 fragment constants
    const int aRow0 = qh * 32 + (lane & 15);           // slab 0 row
    const int aCb   = lane >> 4;
    const int bRowOff = (lane & 7) + ((lane >> 4) << 3);
    const int bCb   = (lane >> 3) & 1;
    // GEMM2 fragment constants
    const int pRow  = lane & 15;                        // + s*16
    const int pCb   = lane >> 4;
    const int fRowOff = (lane & 7) + (((lane >> 3) & 1) << 3);
    const int fCb   = (lane >> 4) & 1;

    float o[32][4];
    #pragma unroll
    for (int j = 0; j < 32; j++) { o[j][0] = o[j][1] = o[j][2] = o[j][3] = 0.f; }
    float la[2][2] = {{0.f, 0.f}, {0.f, 0.f}};          // [slab][rowhalf] partial l

    if (ntg > 0) { STAGE_TILE(Kg, Kbase, g * 64); STAGE_TILE(Fg, Fbase, g * 64); }

    for (int t = 0; t < ntg; t++) {
        const int k0 = (g + 2 * t) * 64;

        asm volatile("cp.async.wait_group 1;" ::: "memory");     // K ready
        asm volatile("bar.sync %0, 128;" :: "r"(barid) : "memory");

        // ---------- GEMM1: warp computes S[32q x 32k] ----------
        float s[2][4][4];
        #pragma unroll
        for (int i = 0; i < 2; i++)
            #pragma unroll
            for (int j = 0; j < 4; j++)
                s[i][j][0] = s[i][j][1] = s[i][j][2] = s[i][j][3] = 0.f;

        #pragma unroll
        for (int ks = 0; ks < 16; ks++) {
            uint32_t a[2][4];
            #pragma unroll
            for (int sl = 0; sl < 2; sl++) {
                int row = aRow0 + sl * 16;
                ldsm4(a[sl][0], a[sl][1], a[sl][2], a[sl][3],
                      sb + QOFF + row * 512 + (((2 * ks + aCb) ^ (row & 7)) << 4));
            }
            #pragma unroll
            for (int nc = 0; nc < 2; nc++) {
                int row = kh * 32 + nc * 16 + bRowOff;
                uint32_t r0, r1, r2, r3;
                ldsm4(r0, r1, r2, r3, Kbase + row * 512 + (((2 * ks + bCb) ^ (row & 7)) << 4));
                #pragma unroll
                for (int sl = 0; sl < 2; sl++) {
                    mma16816(s[sl][2 * nc],     a[sl][0], a[sl][1], a[sl][2], a[sl][3], r0, r1);
                    mma16816(s[sl][2 * nc + 1], a[sl][0], a[sl][1], a[sl][2], a[sl][3], r2, r3);
                }
            }
        }

        asm volatile("bar.sync %0, 128;" :: "r"(barid) : "memory"); // K consumed
        if (t + 1 < ntg) STAGE_TILE(Kg, Kbase, (g + 2 * (t + 1)) * 64);

        // ---------- exp (bounded scores -> no max), l accum, P -> smem ----------
        const bool tail = (k0 + 64 > kcnt);
        #pragma unroll
        for (int sl = 0; sl < 2; sl++) {
            int qrow = qh * 32 + sl * 16 + (lane >> 2);
            #pragma unroll
            for (int j = 0; j < 4; j++) {
                int nc = j >> 1, h = j & 1;
                float e0, e1, e2, e3;
                if (tail) {
                    int kb = k0 + kh * 32 + nc * 16 + h * 8 + 2 * (lane & 3);
                    e0 = (kb     < kcnt) ? __expf(s[sl][j][0]) : 0.f;
                    e1 = (kb + 1 < kcnt) ? __expf(s[sl][j][1]) : 0.f;
                    e2 = (kb     < kcnt) ? __expf(s[sl][j][2]) : 0.f;
                    e3 = (kb + 1 < kcnt) ? __expf(s[sl][j][3]) : 0.f;
                } else {
                    e0 = __expf(s[sl][j][0]);
                    e1 = __expf(s[sl][j][1]);
                    e2 = __expf(s[sl][j][2]);
                    e3 = __expf(s[sl][j][3]);
                }
                la[sl][0] += e0 + e1;
                la[sl][1] += e2 + e3;
                int unit = kh * 4 + nc * 2 + h;
                uint32_t a0 = Pbase + qrow * 128 + ((unit ^ (qrow & 7)) << 4) + ((lane & 3) << 2);
                int qrow1 = qrow + 8;
                uint32_t a1 = Pbase + qrow1 * 128 + ((unit ^ (qrow1 & 7)) << 4) + ((lane & 3) << 2);
                *(uint32_t*)(sm + (a0 - sb)) = pack_bf2(e0, e1);
                *(uint32_t*)(sm + (a1 - sb)) = pack_bf2(e2, e3);
            }
        }

        // F ready + P visible to group
        if (t + 1 < ntg) asm volatile("cp.async.wait_group 1;" ::: "memory");
        else             asm volatile("cp.async.wait_group 0;" ::: "memory");
        asm volatile("bar.sync %0, 128;" :: "r"(barid) : "memory");

        // ---------- GEMM2: warp owns d-section [wg*64, wg*64+64), all 64 q ----------
        #pragma unroll
        for (int kk = 0; kk < 4; kk++) {
            uint32_t ap[4][4];
            #pragma unroll
            for (int sl = 0; sl < 4; sl++) {
                int row = sl * 16 + pRow;
                ldsm4(ap[sl][0], ap[sl][1], ap[sl][2], ap[sl][3],
                      Pbase + row * 128 + (((2 * kk + pCb) ^ (row & 7)) << 4));
            }
            #pragma unroll
            for (int nb = 0; nb < 4; nb++) {
                int pg = wg * 4 + nb;                   // d16 block
                int row = kk * 16 + fRowOff;
                uint32_t r0, r1, r2, r3;
                ldsm4t(r0, r1, r2, r3, Fbase + row * 512 + (((2 * pg + fCb) ^ (row & 7)) << 4));
                #pragma unroll
                for (int sl = 0; sl < 4; sl++) {
                    mma16816(o[sl * 8 + 2 * nb],     ap[sl][0], ap[sl][1], ap[sl][2], ap[sl][3], r0, r1);
                    mma16816(o[sl * 8 + 2 * nb + 1], ap[sl][0], ap[sl][1], ap[sl][2], ap[sl][3], r2, r3);
                }
            }
        }

        asm volatile("bar.sync %0, 128;" :: "r"(barid) : "memory"); // F + P consumed
        if (t + 1 < ntg) STAGE_TILE(Fg, Fbase, (g + 2 * (t + 1)) * 64);
    }

    // ---------- l: quad-reduce, add into shared ----------
    #pragma unroll
    for (int sl = 0; sl < 2; sl++)
        #pragma unroll
        for (int rh = 0; rh < 2; rh++) {
            float v = la[sl][rh];
            v += __shfl_xor_sync(0xffffffffu, v, 1);
            v += __shfl_xor_sync(0xffffffffu, v, 2);
            la[sl][rh] = v;
        }
    if ((lane & 3) == 0) {
        float* slp = (float*)(sm + SL_OFF);
        #pragma unroll
        for (int sl = 0; sl < 2; sl++)
            #pragma unroll
            for (int rh = 0; rh < 2; rh++)
                atomicAdd(&slp[qh * 32 + sl * 16 + rh * 8 + (lane >> 2)], la[sl][rh]);
    }
    __syncthreads();   // l complete; K/F regions retired -> Obuf reuse safe

    // ---------- O merge: group1 writes, group0 adds+scales ----------
    float* Ob = (float*)(sm + OB_OFF);
    if (g == 1) {
        #pragma unroll
        for (int sl = 0; sl < 4; sl++) {
            int q = sl * 16 + (lane >> 2);
            #pragma unroll
            for (int nb2 = 0; nb2 < 8; nb2++) {
                int d = wg * 64 + nb2 * 8 + 2 * (lane & 3);
                *(float2*)(Ob + q * OSTRIDE + d)       = make_float2(o[sl*8+nb2][0], o[sl*8+nb2][1]);
                *(float2*)(Ob + (q + 8) * OSTRIDE + d) = make_float2(o[sl*8+nb2][2], o[sl*8+nb2][3]);
            }
        }
    }
    __syncthreads();
    if (g == 0) {
        const float* slp = (const float*)(sm + SL_OFF);
        #pragma unroll
        for (int sl = 0; sl < 4; sl++) {
            int q = sl * 16 + (lane >> 2);
            float il0 = 1.0f / slp[q];
            float il1 = 1.0f / slp[q + 8];
            #pragma unroll
            for (int nb2 = 0; nb2 < 8; nb2++) {
                int d = wg * 64 + nb2 * 8 + 2 * (lane & 3);
                float2 x0 = *(float2*)(Ob + q * OSTRIDE + d);
                float2 x1 = *(float2*)(Ob + (q + 8) * OSTRIDE + d);
                *(float2*)(Ob + q * OSTRIDE + d) =
                    make_float2((o[sl*8+nb2][0] + x0.x) * il0, (o[sl*8+nb2][1] + x0.y) * il0);
                *(float2*)(Ob + (q + 8) * OSTRIDE + d) =
                    make_float2((o[sl*8+nb2][2] + x1.x) * il1, (o[sl*8+nb2][3] + x1.y) * il1);
            }
        }
    }
    __syncthreads();

    // ---------- coalesced scatter into hole columns ----------
    {
        const int q = tid & 63;
        const int n = ((const int*)(sm + QN_OFF))[q];
        float* ob = out + ((size_t)b * 768 + 512) * NPIX;
        if (n >= 0) {
            for (int r = tid >> 6; r < 256; r += 4)
                ob[(size_t)r * NPIX + n] = Ob[q * OSTRIDE + r];
        }
    }
}

// ---------------- launch ------------------------------------------------------
extern "C" void kernel_launch(void* const* d_in, const int* in_sizes, int n_in,
                              void* d_out, int out_size)
{
    const float* x    = (const float*)d_in[0];
    const void*  mask = d_in[1];
    float*       out  = (float*)d_out;

    const int N = in_sizes[1];                  // 4096
    const int B = in_sizes[0] / (512 * N);      // 8

    k_compact<<<1, 128>>>(mask, N);
    k_prep<<<dim3(N / 32, B), 256>>>(x, out);
    cudaFuncSetAttribute(k_attn, cudaFuncAttributeMaxDynamicSharedMemorySize, SMB);
    k_attn<<<dim3(N / 64, B), 256, SMB>>>(out);
}

// round 8
// speedup vs baseline: 17.3486x; 1.4431x over previous
#include <cuda_runtime.h>
#include <cuda_bf16.h>
#include <cstdint>
#include <cstddef>

// Fixed problem shapes: x: [B, 512, 64, 64] f32, mask: [64, 64] bool. d=256, N=4096.
#define BMAX   8
#define DDIM   256
#define NPIX   4096

// ---------------- scratch (device globals) ------------------------------------
__device__ __nv_bfloat16 g_Qh[(size_t)BMAX * NPIX * DDIM];  // normalized latter, hole rows [b][qpos][d]
__device__ __nv_bfloat16 g_Kh[(size_t)BMAX * NPIX * DDIM];  // normalized latter, known rows [b][kpos][d]
__device__ __nv_bfloat16 g_Fh[(size_t)BMAX * NPIX * DDIM];  // former, known rows [b][kpos][d]
__device__ int   g_qidx[NPIX];
__device__ int   g_pos [NPIX];
__device__ int   g_isq [NPIX];
__device__ int   g_cnt [2];                                 // [0]=qcnt, [1]=kcnt

// ---------------- ptx helpers --------------------------------------------------
__device__ __forceinline__ uint32_t smem_u32(const void* p) {
    uint32_t a;
    asm("{ .reg .u64 t; cvta.to.shared.u64 t, %1; cvt.u32.u64 %0, t; }" : "=r"(a) : "l"(p));
    return a;
}
__device__ __forceinline__ void ldsm4(uint32_t& r0, uint32_t& r1, uint32_t& r2, uint32_t& r3, uint32_t a) {
    asm volatile("ldmatrix.sync.aligned.m8n8.x4.shared.b16 {%0,%1,%2,%3}, [%4];"
                 : "=r"(r0), "=r"(r1), "=r"(r2), "=r"(r3) : "r"(a));
}
__device__ __forceinline__ void ldsm4t(uint32_t& r0, uint32_t& r1, uint32_t& r2, uint32_t& r3, uint32_t a) {
    asm volatile("ldmatrix.sync.aligned.m8n8.x4.trans.shared.b16 {%0,%1,%2,%3}, [%4];"
                 : "=r"(r0), "=r"(r1), "=r"(r2), "=r"(r3) : "r"(a));
}
__device__ __forceinline__ void mma16816(float* c, uint32_t a0, uint32_t a1, uint32_t a2, uint32_t a3,
                                         uint32_t b0, uint32_t b1) {
    asm volatile("mma.sync.aligned.m16n8k16.row.col.f32.bf16.bf16.f32 "
                 "{%0,%1,%2,%3}, {%4,%5,%6,%7}, {%8,%9}, {%0,%1,%2,%3};"
                 : "+f"(c[0]), "+f"(c[1]), "+f"(c[2]), "+f"(c[3])
                 : "r"(a0), "r"(a1), "r"(a2), "r"(a3), "r"(b0), "r"(b1));
}
__device__ __forceinline__ uint32_t pack_bf2(float lo, float hi) {
    __nv_bfloat162 h = __floats2bfloat162_rn(lo, hi);
    return *(uint32_t*)&h;
}

// ---------------- kernel 0: deterministic mask compaction (parallel) ----------
// 128 threads, 32 pixels each. Sniff (bool-bytes vs int32) is a parallel
// OR-reduce; per-thread flags condensed into a 32-bit register bitmask.
__global__ void k_compact(const void* __restrict__ maskp, int N)
{
    __shared__ int cq[129];
    __shared__ int s_isu8;
    const int CH = N / 128;                      // 32
    const int t  = threadIdx.x;

    if (t == 0) s_isu8 = 0;
    __syncthreads();

    // parallel sniff: any 32-bit word > 1 => byte-packed bools
    {
        const unsigned* w = (const unsigned*)maskp;
        unsigned acc = 0;
        #pragma unroll
        for (int i = t; i < NPIX / 4; i += 128) acc |= w[i];
        if (acc > 1u) s_isu8 = 1;                // benign race (same value)
    }
    __syncthreads();
    const int isu8 = s_isu8;
    const unsigned char* mb = (const unsigned char*)maskp;
    const int*           mw = (const int*)maskp;

    // condense this thread's 32 flags into a bitmask (mask read once)
    unsigned bits = 0;
    #pragma unroll
    for (int i = 0; i < 32; i++) {
        int gi = t * CH + i;
        int f  = isu8 ? (mb[gi] != 0) : (mw[gi] != 0);
        bits |= (unsigned)f << i;
    }
    cq[t] = __popc(bits);
    __syncthreads();
    if (t == 0) {
        int acc = 0;
        for (int i = 0; i < 128; i++) { int v = cq[i]; cq[i] = acc; acc += v; }
        cq[128] = acc;
        g_cnt[0] = acc;
        g_cnt[1] = N - acc;
    }
    __syncthreads();

    int q = cq[t];
    int k = t * CH - cq[t];
    #pragma unroll
    for (int i = 0; i < 32; i++) {
        int gi = t * CH + i;
        if ((bits >> i) & 1u) { g_qidx[q] = gi; g_pos[gi] = q; g_isq[gi] = 1; q++; }
        else                  {                 g_pos[gi] = k; g_isq[gi] = 0; k++; }
    }
}

// ---------------- kernel 1: fused prep ----------------------------------------
// grid (N/32, B), 256 threads. Single pass over x:
//   - copies former+latter into out channels [0,512)
//   - zero-fills out channels [512,768)
//   - computes column norms of latter, packs bf16 Q/K (compacted, row-major)
//   - packs bf16 F (compacted, row-major)
__global__ void k_prep(const float* __restrict__ x, float* __restrict__ out)
{
    __shared__ float tile[256][33];
    __shared__ float psum[8][32];
    __shared__ float inv_s[32];
    __shared__ int   pp[32], mq[32];

    const int b  = blockIdx.y;
    const int n0 = blockIdx.x * 32;
    const int tx = threadIdx.x & 31;
    const int ty = threadIdx.x >> 5;

    const float* lat = x + ((size_t)b * 512 + 256) * NPIX;
    float* outb = out + (size_t)b * 768 * NPIX;

    // phase 1: latter -> smem + copy out + zero shift rows
    for (int r = ty; r < 256; r += 8) {
        float v = lat[(size_t)r * NPIX + n0 + tx];
        tile[r][tx] = v;
        outb[(size_t)(256 + r) * NPIX + n0 + tx] = v;
        outb[(size_t)(512 + r) * NPIX + n0 + tx] = 0.f;
    }
    if (threadIdx.x < 32) { pp[tx] = g_pos[n0 + tx]; mq[tx] = g_isq[n0 + tx]; }
    __syncthreads();

    float ss = 0.f;
    for (int r = ty * 32; r < ty * 32 + 32; r++) { float v = tile[r][tx]; ss += v * v; }
    psum[ty][tx] = ss;
    __syncthreads();
    if (threadIdx.x < 32) {
        float s = 0.f;
        #pragma unroll
        for (int i = 0; i < 8; i++) s += psum[i][tx];
        inv_s[tx] = 1.0f / (sqrtf(s) + 1e-8f);
    }
    __syncthreads();

    const float inv = inv_s[tx];
    const int   p   = pp[tx];
    const int   isq = mq[tx];
    {
        __nv_bfloat16* dst = (isq ? g_Qh : g_Kh) + ((size_t)b * NPIX + p) * DDIM;
        #pragma unroll
        for (int i = 0; i < 4; i++) {
            int r8 = ty * 8 + i * 64;
            uint32_t w0 = pack_bf2(tile[r8+0][tx]*inv, tile[r8+1][tx]*inv);
            uint32_t w1 = pack_bf2(tile[r8+2][tx]*inv, tile[r8+3][tx]*inv);
            uint32_t w2 = pack_bf2(tile[r8+4][tx]*inv, tile[r8+5][tx]*inv);
            uint32_t w3 = pack_bf2(tile[r8+6][tx]*inv, tile[r8+7][tx]*inv);
            *(uint4*)(dst + r8) = make_uint4(w0, w1, w2, w3);
        }
    }

    // phase 2: former -> smem + copy out + pack F
    __syncthreads();
    const float* fm = x + (size_t)b * 512 * NPIX;
    for (int r = ty; r < 256; r += 8) {
        float v = fm[(size_t)r * NPIX + n0 + tx];
        tile[r][tx] = v;
        outb[(size_t)r * NPIX + n0 + tx] = v;
    }
    __syncthreads();
    if (!isq) {
        __nv_bfloat16* df = g_Fh + ((size_t)b * NPIX + p) * DDIM;
        #pragma unroll
        for (int i = 0; i < 4; i++) {
            int r8 = ty * 8 + i * 64;
            uint32_t w0 = pack_bf2(tile[r8+0][tx], tile[r8+1][tx]);
            uint32_t w1 = pack_bf2(tile[r8+2][tx], tile[r8+3][tx]);
            uint32_t w2 = pack_bf2(tile[r8+4][tx], tile[r8+5][tx]);
            uint32_t w3 = pack_bf2(tile[r8+6][tx], tile[r8+7][tx]);
            *(uint4*)(df + r8) = make_uint4(w0, w1, w2, w3);
        }
    }
}

// ---------------- kernel 2: bf16 tensor-core attention (no online max) --------
// 256 threads = 2 groups x 4 warps; group g handles key tiles g, g+2, ...
// Scores are cosines (<=1) -> exp(s) directly, no running max, no rescale.
// GEMM1: 2x2 warp layout (32q x 32k per warp). P staged through smem (bf16).
// GEMM2: d-split across the 4 warps (each warp owns 64 d channels; F read 1x).
// Merge: l via shared atomicAdd; O via smem sum; scale once; scatter.
#define QOFF    0                      // bf16 [64][256] swizzled      32768
#define QN_OFF  32768                  // int[64]                        256
#define SL_OFF  33024                  // float[64] l accumulators       256
#define KOFF    33280                  // bf16 K tiles, per group 32768
#define FOFF    98816                  // bf16 F tiles, per group 32768
#define POFF    164352                 // bf16 P [64][64] per group 8192
#define OB_OFF  33280                  // f32 [64][258] (reuses K/F region)
#define OSTRIDE 258
#define SMB     180736

#define STAGE_TILE(SRC, DSTB, K0)                                               \
    do {                                                                        \
        _Pragma("unroll")                                                       \
        for (int _i = 0; _i < 16; _i++) {                                       \
            int _idx = tg + _i * 128;                                           \
            int _row = _idx >> 5, _ch = _idx & 31;                              \
            const __nv_bfloat16* _gp = (SRC) + ((size_t)((K0) + _row) * DDIM + _ch * 8); \
            uint32_t _sa = (DSTB) + _row * 512 + ((_ch ^ (_row & 7)) << 4);     \
            asm volatile("cp.async.cg.shared.global [%0], [%1], 16;"            \
                         :: "r"(_sa), "l"(_gp) : "memory");                     \
        }                                                                       \
        asm volatile("cp.async.commit_group;" ::: "memory");                    \
    } while (0)

__global__ void __launch_bounds__(256, 1)
k_attn(float* __restrict__ out)
{
    extern __shared__ char sm[];
    const uint32_t sb = smem_u32(sm);

    const int b    = blockIdx.y;
    const int qcnt = g_cnt[0];
    const int kcnt = g_cnt[1];
    const int q0   = blockIdx.x * 64;
    if (q0 >= qcnt) return;

    const int tid  = threadIdx.x;
    const int lane = tid & 31;
    const int warp = tid >> 5;
    const int g    = warp >> 2;     // key group 0/1
    const int wg   = warp & 3;      // warp within group
    const int qh   = wg & 1;        // GEMM1: query half (32 rows)
    const int kh   = wg >> 1;       // GEMM1: key half (32 cols)
    const int tg   = tid & 127;

    // ---- stage Q tile (swizzled bf16 [64][256]); zero l accumulators ----
    {
        const __nv_bfloat16* Qg = g_Qh + (size_t)b * NPIX * DDIM;
        #pragma unroll
        for (int i = 0; i < 8; i++) {
            int idx = tid + i * 256;
            int row = idx >> 5, ch = idx & 31;
            uint4 v = make_uint4(0u, 0u, 0u, 0u);
            if (q0 + row < qcnt)
                v = *(const uint4*)(Qg + ((size_t)(q0 + row) * DDIM + ch * 8));
            *(uint4*)(sm + QOFF + row * 512 + ((ch ^ (row & 7)) << 4)) = v;
        }
        if (tid < 64) {
            ((int*)(sm + QN_OFF))[tid] = (q0 + tid < qcnt) ? g_qidx[q0 + tid] : -1;
            ((float*)(sm + SL_OFF))[tid] = 0.f;
        }
    }
    __syncthreads();

    const __nv_bfloat16* Kg = g_Kh + (size_t)b * NPIX * DDIM;
    const __nv_bfloat16* Fg = g_Fh + (size_t)b * NPIX * DDIM;
    const int ntt = (kcnt + 63) >> 6;
    const int ntg = (g == 0) ? ((ntt + 1) >> 1) : (ntt >> 1);

    const uint32_t Kbase = sb + KOFF + g * 32768;
    const uint32_t Fbase = sb + FOFF + g * 32768;
    const uint32_t Pbase = sb + POFF + g * 8192;
    const int barid = 1 + g;

    // GEMM1 fragment constants
    const int aRow0 = qh * 32 + (lane & 15);           // slab 0 row
    const int aCb   = lane >> 4;
    const int bRowOff = (lane & 7) + ((lane >> 4) << 3);
    const int bCb   = (lane >> 3) & 1;
    // GEMM2 fragment constants
    const int pRow  = lane & 15;                        // + s*16
    const int pCb   = lane >> 4;
    const int fRowOff = (lane & 7) + (((lane >> 3) & 1) << 3);
    const int fCb   = (lane >> 4) & 1;

    float o[32][4];
    #pragma unroll
    for (int j = 0; j < 32; j++) { o[j][0] = o[j][1] = o[j][2] = o[j][3] = 0.f; }
    float la[2][2] = {{0.f, 0.f}, {0.f, 0.f}};          // [slab][rowhalf] partial l

    if (ntg > 0) { STAGE_TILE(Kg, Kbase, g * 64); STAGE_TILE(Fg, Fbase, g * 64); }

    for (int t = 0; t < ntg; t++) {
        const int k0 = (g + 2 * t) * 64;

        asm volatile("cp.async.wait_group 1;" ::: "memory");     // K ready
        asm volatile("bar.sync %0, 128;" :: "r"(barid) : "memory");

        // ---------- GEMM1: warp computes S[32q x 32k] ----------
        float s[2][4][4];
        #pragma unroll
        for (int i = 0; i < 2; i++)
            #pragma unroll
            for (int j = 0; j < 4; j++)
                s[i][j][0] = s[i][j][1] = s[i][j][2] = s[i][j][3] = 0.f;

        #pragma unroll
        for (int ks = 0; ks < 16; ks++) {
            uint32_t a[2][4];
            #pragma unroll
            for (int sl = 0; sl < 2; sl++) {
                int row = aRow0 + sl * 16;
                ldsm4(a[sl][0], a[sl][1], a[sl][2], a[sl][3],
                      sb + QOFF + row * 512 + (((2 * ks + aCb) ^ (row & 7)) << 4));
            }
            #pragma unroll
            for (int nc = 0; nc < 2; nc++) {
                int row = kh * 32 + nc * 16 + bRowOff;
                uint32_t r0, r1, r2, r3;
                ldsm4(r0, r1, r2, r3, Kbase + row * 512 + (((2 * ks + bCb) ^ (row & 7)) << 4));
                #pragma unroll
                for (int sl = 0; sl < 2; sl++) {
                    mma16816(s[sl][2 * nc],     a[sl][0], a[sl][1], a[sl][2], a[sl][3], r0, r1);
                    mma16816(s[sl][2 * nc + 1], a[sl][0], a[sl][1], a[sl][2], a[sl][3], r2, r3);
                }
            }
        }

        asm volatile("bar.sync %0, 128;" :: "r"(barid) : "memory"); // K consumed
        if (t + 1 < ntg) STAGE_TILE(Kg, Kbase, (g + 2 * (t + 1)) * 64);

        // ---------- exp (bounded scores -> no max), l accum, P -> smem ----------
        const bool tail = (k0 + 64 > kcnt);
        #pragma unroll
        for (int sl = 0; sl < 2; sl++) {
            int qrow = qh * 32 + sl * 16 + (lane >> 2);
            #pragma unroll
            for (int j = 0; j < 4; j++) {
                int nc = j >> 1, h = j & 1;
                float e0, e1, e2, e3;
                if (tail) {
                    int kb = k0 + kh * 32 + nc * 16 + h * 8 + 2 * (lane & 3);
                    e0 = (kb     < kcnt) ? __expf(s[sl][j][0]) : 0.f;
                    e1 = (kb + 1 < kcnt) ? __expf(s[sl][j][1]) : 0.f;
                    e2 = (kb     < kcnt) ? __expf(s[sl][j][2]) : 0.f;
                    e3 = (kb + 1 < kcnt) ? __expf(s[sl][j][3]) : 0.f;
                } else {
                    e0 = __expf(s[sl][j][0]);
                    e1 = __expf(s[sl][j][1]);
                    e2 = __expf(s[sl][j][2]);
                    e3 = __expf(s[sl][j][3]);
                }
                la[sl][0] += e0 + e1;
                la[sl][1] += e2 + e3;
                int unit = kh * 4 + nc * 2 + h;
                uint32_t a0 = Pbase + qrow * 128 + ((unit ^ (qrow & 7)) << 4) + ((lane & 3) << 2);
                int qrow1 = qrow + 8;
                uint32_t a1 = Pbase + qrow1 * 128 + ((unit ^ (qrow1 & 7)) << 4) + ((lane & 3) << 2);
                *(uint32_t*)(sm + (a0 - sb)) = pack_bf2(e0, e1);
                *(uint32_t*)(sm + (a1 - sb)) = pack_bf2(e2, e3);
            }
        }

        // F ready + P visible to group
        if (t + 1 < ntg) asm volatile("cp.async.wait_group 1;" ::: "memory");
        else             asm volatile("cp.async.wait_group 0;" ::: "memory");
        asm volatile("bar.sync %0, 128;" :: "r"(barid) : "memory");

        // ---------- GEMM2: warp owns d-section [wg*64, wg*64+64), all 64 q ----------
        #pragma unroll
        for (int kk = 0; kk < 4; kk++) {
            uint32_t ap[4][4];
            #pragma unroll
            for (int sl = 0; sl < 4; sl++) {
                int row = sl * 16 + pRow;
                ldsm4(ap[sl][0], ap[sl][1], ap[sl][2], ap[sl][3],
                      Pbase + row * 128 + (((2 * kk + pCb) ^ (row & 7)) << 4));
            }
            #pragma unroll
            for (int nb = 0; nb < 4; nb++) {
                int pg = wg * 4 + nb;                   // d16 block
                int row = kk * 16 + fRowOff;
                uint32_t r0, r1, r2, r3;
                ldsm4t(r0, r1, r2, r3, Fbase + row * 512 + (((2 * pg + fCb) ^ (row & 7)) << 4));
                #pragma unroll
                for (int sl = 0; sl < 4; sl++) {
                    mma16816(o[sl * 8 + 2 * nb],     ap[sl][0], ap[sl][1], ap[sl][2], ap[sl][3], r0, r1);
                    mma16816(o[sl * 8 + 2 * nb + 1], ap[sl][0], ap[sl][1], ap[sl][2], ap[sl][3], r2, r3);
                }
            }
        }

        asm volatile("bar.sync %0, 128;" :: "r"(barid) : "memory"); // F + P consumed
        if (t + 1 < ntg) STAGE_TILE(Fg, Fbase, (g + 2 * (t + 1)) * 64);
    }

    // ---------- l: quad-reduce, add into shared ----------
    #pragma unroll
    for (int sl = 0; sl < 2; sl++)
        #pragma unroll
        for (int rh = 0; rh < 2; rh++) {
            float v = la[sl][rh];
            v += __shfl_xor_sync(0xffffffffu, v, 1);
            v += __shfl_xor_sync(0xffffffffu, v, 2);
            la[sl][rh] = v;
        }
    if ((lane & 3) == 0) {
        float* slp = (float*)(sm + SL_OFF);
        #pragma unroll
        for (int sl = 0; sl < 2; sl++)
            #pragma unroll
            for (int rh = 0; rh < 2; rh++)
                atomicAdd(&slp[qh * 32 + sl * 16 + rh * 8 + (lane >> 2)], la[sl][rh]);
    }
    __syncthreads();   // l complete; K/F regions retired -> Obuf reuse safe

    // ---------- O merge: group1 writes, group0 adds+scales ----------
    float* Ob = (float*)(sm + OB_OFF);
    if (g == 1) {
        #pragma unroll
        for (int sl = 0; sl < 4; sl++) {
            int q = sl * 16 + (lane >> 2);
            #pragma unroll
            for (int nb2 = 0; nb2 < 8; nb2++) {
                int d = wg * 64 + nb2 * 8 + 2 * (lane & 3);
                *(float2*)(Ob + q * OSTRIDE + d)       = make_float2(o[sl*8+nb2][0], o[sl*8+nb2][1]);
                *(float2*)(Ob + (q + 8) * OSTRIDE + d) = make_float2(o[sl*8+nb2][2], o[sl*8+nb2][3]);
            }
        }
    }
    __syncthreads();
    if (g == 0) {
        const float* slp = (const float*)(sm + SL_OFF);
        #pragma unroll
        for (int sl = 0; sl < 4; sl++) {
            int q = sl * 16 + (lane >> 2);
            float il0 = 1.0f / slp[q];
            float il1 = 1.0f / slp[q + 8];
            #pragma unroll
            for (int nb2 = 0; nb2 < 8; nb2++) {
                int d = wg * 64 + nb2 * 8 + 2 * (lane & 3);
                float2 x0 = *(float2*)(Ob + q * OSTRIDE + d);
                float2 x1 = *(float2*)(Ob + (q + 8) * OSTRIDE + d);
                *(float2*)(Ob + q * OSTRIDE + d) =
                    make_float2((o[sl*8+nb2][0] + x0.x) * il0, (o[sl*8+nb2][1] + x0.y) * il0);
                *(float2*)(Ob + (q + 8) * OSTRIDE + d) =
                    make_float2((o[sl*8+nb2][2] + x1.x) * il1, (o[sl*8+nb2][3] + x1.y) * il1);
            }
        }
    }
    __syncthreads();

    // ---------- coalesced scatter into hole columns ----------
    {
        const int q = tid & 63;
        const int n = ((const int*)(sm + QN_OFF))[q];
        float* ob = out + ((size_t)b * 768 + 512) * NPIX;
        if (n >= 0) {
            for (int r = tid >> 6; r < 256; r += 4)
                ob[(size_t)r * NPIX + n] = Ob[q * OSTRIDE + r];
        }
    }
}

// ---------------- launch ------------------------------------------------------
extern "C" void kernel_launch(void* const* d_in, const int* in_sizes, int n_in,
                              void* d_out, int out_size)
{
    const float* x    = (const float*)d_in[0];
    const void*  mask = d_in[1];
    float*       out  = (float*)d_out;

    const int N = in_sizes[1];                  // 4096
    const int B = in_sizes[0] / (512 * N);      // 8

    k_compact<<<1, 128>>>(mask, N);
    k_prep<<<dim3(N / 32, B), 256>>>(x, out);
    cudaFuncSetAttribute(k_attn, cudaFuncAttributeMaxDynamicSharedMemorySize, SMB);
    k_attn<<<dim3(N / 64, B), 256, SMB>>>(out);
}

// round 9
// speedup vs baseline: 19.9632x; 1.1507x over previous
#include <cuda_runtime.h>
#include <cuda_bf16.h>
#include <cstdint>
#include <cstddef>

// Fixed problem shapes: x: [B, 512, 64, 64] f32, mask: [64, 64] bool. d=256, N=4096.
#define BMAX   8
#define DDIM   256
#define NPIX   4096

// ---------------- scratch (device globals) ------------------------------------
__device__ __nv_bfloat16 g_Qh[(size_t)BMAX * NPIX * DDIM];  // normalized latter, hole rows [b][qpos][d]
__device__ __nv_bfloat16 g_Kh[(size_t)BMAX * NPIX * DDIM];  // normalized latter, known rows [b][kpos][d]
__device__ __nv_bfloat16 g_Fh[(size_t)BMAX * NPIX * DDIM];  // former, known rows [b][kpos][d]
__device__ int   g_qidx[NPIX];
__device__ int   g_pos [NPIX];
__device__ int   g_isq [NPIX];
__device__ int   g_cnt [2];                                 // [0]=qcnt, [1]=kcnt

// ---------------- ptx helpers --------------------------------------------------
__device__ __forceinline__ uint32_t smem_u32(const void* p) {
    uint32_t a;
    asm("{ .reg .u64 t; cvta.to.shared.u64 t, %1; cvt.u32.u64 %0, t; }" : "=r"(a) : "l"(p));
    return a;
}
__device__ __forceinline__ void ldsm4(uint32_t& r0, uint32_t& r1, uint32_t& r2, uint32_t& r3, uint32_t a) {
    asm volatile("ldmatrix.sync.aligned.m8n8.x4.shared.b16 {%0,%1,%2,%3}, [%4];"
                 : "=r"(r0), "=r"(r1), "=r"(r2), "=r"(r3) : "r"(a));
}
__device__ __forceinline__ void ldsm4t(uint32_t& r0, uint32_t& r1, uint32_t& r2, uint32_t& r3, uint32_t a) {
    asm volatile("ldmatrix.sync.aligned.m8n8.x4.trans.shared.b16 {%0,%1,%2,%3}, [%4];"
                 : "=r"(r0), "=r"(r1), "=r"(r2), "=r"(r3) : "r"(a));
}
__device__ __forceinline__ void mma16816(float* c, uint32_t a0, uint32_t a1, uint32_t a2, uint32_t a3,
                                         uint32_t b0, uint32_t b1) {
    asm volatile("mma.sync.aligned.m16n8k16.row.col.f32.bf16.bf16.f32 "
                 "{%0,%1,%2,%3}, {%4,%5,%6,%7}, {%8,%9}, {%0,%1,%2,%3};"
                 : "+f"(c[0]), "+f"(c[1]), "+f"(c[2]), "+f"(c[3])
                 : "r"(a0), "r"(a1), "r"(a2), "r"(a3), "r"(b0), "r"(b1));
}
__device__ __forceinline__ uint32_t pack_bf2(float lo, float hi) {
    __nv_bfloat162 h = __floats2bfloat162_rn(lo, hi);
    return *(uint32_t*)&h;
}

// ---------------- kernel 0: mask compaction (warp-scan) -----------------------
// 128 threads = 4 warps; each thread owns 32 pixels condensed to a bitmask.
// Prefix via shfl inclusive scan + 4-warp combine (no serial thread-0 loop).
__global__ void k_compact(const void* __restrict__ maskp, int N)
{
    __shared__ int wsum[4];
    __shared__ int s_isu8;
    const int t    = threadIdx.x;
    const int lane = t & 31;
    const int wid  = t >> 5;

    if (t == 0) s_isu8 = 0;
    __syncthreads();

    // parallel sniff: any 32-bit word > 1 => byte-packed bools
    {
        const unsigned* w = (const unsigned*)maskp;
        unsigned acc = 0;
        #pragma unroll
        for (int i = 0; i < 8; i++) acc |= w[t + i * 128];
        if (acc > 1u) s_isu8 = 1;                // benign race (same value)
    }
    __syncthreads();
    const int isu8 = s_isu8;

    // condense this thread's 32 flags into a bitmask
    unsigned bits = 0;
    if (isu8) {
        const unsigned* w = (const unsigned*)maskp;   // 8 words = 32 bytes
        #pragma unroll
        for (int i = 0; i < 8; i++) {
            unsigned v = w[t * 8 + i];
            #pragma unroll
            for (int j = 0; j < 4; j++)
                bits |= (unsigned)(((v >> (8 * j)) & 255u) != 0u) << (i * 4 + j);
        }
    } else {
        const uint4* w = (const uint4*)maskp;         // 8 uint4 = 32 ints
        #pragma unroll
        for (int i = 0; i < 8; i++) {
            uint4 v = w[t * 8 + i];
            bits |= (unsigned)(v.x != 0u) << (i * 4 + 0);
            bits |= (unsigned)(v.y != 0u) << (i * 4 + 1);
            bits |= (unsigned)(v.z != 0u) << (i * 4 + 2);
            bits |= (unsigned)(v.w != 0u) << (i * 4 + 3);
        }
    }

    // warp inclusive scan of popc
    int cnt = __popc(bits);
    int inc = cnt;
    #pragma unroll
    for (int off = 1; off < 32; off <<= 1) {
        int v = __shfl_up_sync(0xffffffffu, inc, off);
        if (lane >= off) inc += v;
    }
    if (lane == 31) wsum[wid] = inc;
    __syncthreads();
    int base = 0;
    #pragma unroll
    for (int i = 0; i < 4; i++) base += (i < wid) ? wsum[i] : 0;
    if (t == 0) {
        int tot = wsum[0] + wsum[1] + wsum[2] + wsum[3];
        g_cnt[0] = tot;
        g_cnt[1] = N - tot;
    }

    int q = base + inc - cnt;       // exclusive prefix of masked count
    int k = t * 32 - q;
    #pragma unroll
    for (int i = 0; i < 32; i++) {
        int gi = t * 32 + i;
        if ((bits >> i) & 1u) { g_qidx[q] = gi; g_pos[gi] = q; g_isq[gi] = 1; q++; }
        else                  {                 g_pos[gi] = k; g_isq[gi] = 0; k++; }
    }
}

// ---------------- kernel 1: fused prep (float4 vectorized) --------------------
// grid (N/32, B), 256 threads. Single pass over x:
//   - copies former+latter into out channels [0,512), zero-fills [512,768)
//   - column norms of latter, packs bf16 Q/K and F (compacted, row-major)
__global__ void k_prep(const float* __restrict__ x, float* __restrict__ out)
{
    __shared__ float tile[256][36];     // stride 36: 16B-aligned rows, conflict-free cols
    __shared__ float psum[8][32];
    __shared__ float inv_s[32];
    __shared__ int   pp[32], mq[32];

    const int b  = blockIdx.y;
    const int n0 = blockIdx.x * 32;
    const int tx = threadIdx.x & 31;
    const int ty = threadIdx.x >> 5;
    const int r0 = threadIdx.x >> 3;          // 0..31
    const int c4 = (threadIdx.x & 7) << 2;    // 0,4,...,28

    const float* lat = x + ((size_t)b * 512 + 256) * NPIX;
    float* outb = out + (size_t)b * 768 * NPIX;
    const float4 z4 = make_float4(0.f, 0.f, 0.f, 0.f);

    // phase 1: latter -> smem + copy out + zero shift rows (all float4)
    #pragma unroll
    for (int it = 0; it < 8; it++) {
        int r = it * 32 + r0;
        float4 v = *(const float4*)(lat + (size_t)r * NPIX + n0 + c4);
        *(float4*)(&tile[r][c4]) = v;
        *(float4*)(outb + (size_t)(256 + r) * NPIX + n0 + c4) = v;
        *(float4*)(outb + (size_t)(512 + r) * NPIX + n0 + c4) = z4;
    }
    if (threadIdx.x < 32) { pp[tx] = g_pos[n0 + tx]; mq[tx] = g_isq[n0 + tx]; }
    __syncthreads();

    float ss = 0.f;
    for (int r = ty * 32; r < ty * 32 + 32; r++) { float v = tile[r][tx]; ss += v * v; }
    psum[ty][tx] = ss;
    __syncthreads();
    if (threadIdx.x < 32) {
        float s = 0.f;
        #pragma unroll
        for (int i = 0; i < 8; i++) s += psum[i][tx];
        inv_s[tx] = 1.0f / (sqrtf(s) + 1e-8f);
    }
    __syncthreads();

    const float inv = inv_s[tx];
    const int   p   = pp[tx];
    const int   isq = mq[tx];
    {
        __nv_bfloat16* dst = (isq ? g_Qh : g_Kh) + ((size_t)b * NPIX + p) * DDIM;
        #pragma unroll
        for (int i = 0; i < 4; i++) {
            int r8 = ty * 8 + i * 64;
            uint32_t w0 = pack_bf2(tile[r8+0][tx]*inv, tile[r8+1][tx]*inv);
            uint32_t w1 = pack_bf2(tile[r8+2][tx]*inv, tile[r8+3][tx]*inv);
            uint32_t w2 = pack_bf2(tile[r8+4][tx]*inv, tile[r8+5][tx]*inv);
            uint32_t w3 = pack_bf2(tile[r8+6][tx]*inv, tile[r8+7][tx]*inv);
            *(uint4*)(dst + r8) = make_uint4(w0, w1, w2, w3);
        }
    }

    // phase 2: former -> smem + copy out + pack F
    __syncthreads();
    const float* fm = x + (size_t)b * 512 * NPIX;
    #pragma unroll
    for (int it = 0; it < 8; it++) {
        int r = it * 32 + r0;
        float4 v = *(const float4*)(fm + (size_t)r * NPIX + n0 + c4);
        *(float4*)(&tile[r][c4]) = v;
        *(float4*)(outb + (size_t)r * NPIX + n0 + c4) = v;
    }
    __syncthreads();
    if (!isq) {
        __nv_bfloat16* df = g_Fh + ((size_t)b * NPIX + p) * DDIM;
        #pragma unroll
        for (int i = 0; i < 4; i++) {
            int r8 = ty * 8 + i * 64;
            uint32_t w0 = pack_bf2(tile[r8+0][tx], tile[r8+1][tx]);
            uint32_t w1 = pack_bf2(tile[r8+2][tx], tile[r8+3][tx]);
            uint32_t w2 = pack_bf2(tile[r8+4][tx], tile[r8+5][tx]);
            uint32_t w3 = pack_bf2(tile[r8+6][tx], tile[r8+7][tx]);
            *(uint4*)(df + r8) = make_uint4(w0, w1, w2, w3);
        }
    }
}

// ---------------- kernel 2: bf16 tensor-core attention (no online max) --------
// 256 threads = 2 groups x 4 warps; group g handles key tiles g, g+2, ...
// 3 barriers per iteration (K-consumed folded into F-ready/P-visible barrier).
#define QOFF    0                      // bf16 [64][256] swizzled      32768
#define QN_OFF  32768                  // int[64]                        256
#define SL_OFF  33024                  // float[64] l accumulators       256
#define KOFF    33280                  // bf16 K tiles, per group 32768
#define FOFF    98816                  // bf16 F tiles, per group 32768
#define POFF    164352                 // bf16 P [64][64] per group 8192
#define OB_OFF  33280                  // f32 [64][258] (reuses K/F region)
#define OSTRIDE 258
#define SMB     180736

#define STAGE_TILE(SRC, DSTB, K0)                                               \
    do {                                                                        \
        _Pragma("unroll")                                                       \
        for (int _i = 0; _i < 16; _i++) {                                       \
            int _idx = tg + _i * 128;                                           \
            int _row = _idx >> 5, _ch = _idx & 31;                              \
            const __nv_bfloat16* _gp = (SRC) + ((size_t)((K0) + _row) * DDIM + _ch * 8); \
            uint32_t _sa = (DSTB) + _row * 512 + ((_ch ^ (_row & 7)) << 4);     \
            asm volatile("cp.async.cg.shared.global [%0], [%1], 16;"            \
                         :: "r"(_sa), "l"(_gp) : "memory");                     \
        }                                                                       \
        asm volatile("cp.async.commit_group;" ::: "memory");                    \
    } while (0)

__global__ void __launch_bounds__(256, 1)
k_attn(float* __restrict__ out)
{
    extern __shared__ char sm[];
    const uint32_t sb = smem_u32(sm);

    const int b    = blockIdx.y;
    const int qcnt = g_cnt[0];
    const int kcnt = g_cnt[1];
    const int q0   = blockIdx.x * 64;
    if (q0 >= qcnt) return;

    const int tid  = threadIdx.x;
    const int lane = tid & 31;
    const int warp = tid >> 5;
    const int g    = warp >> 2;     // key group 0/1
    const int wg   = warp & 3;      // warp within group
    const int qh   = wg & 1;        // GEMM1: query half (32 rows)
    const int kh   = wg >> 1;       // GEMM1: key half (32 cols)
    const int tg   = tid & 127;

    // ---- stage Q tile (swizzled bf16 [64][256]); zero l accumulators ----
    {
        const __nv_bfloat16* Qg = g_Qh + (size_t)b * NPIX * DDIM;
        #pragma unroll
        for (int i = 0; i < 8; i++) {
            int idx = tid + i * 256;
            int row = idx >> 5, ch = idx & 31;
            uint4 v = make_uint4(0u, 0u, 0u, 0u);
            if (q0 + row < qcnt)
                v = *(const uint4*)(Qg + ((size_t)(q0 + row) * DDIM + ch * 8));
            *(uint4*)(sm + QOFF + row * 512 + ((ch ^ (row & 7)) << 4)) = v;
        }
        if (tid < 64) {
            ((int*)(sm + QN_OFF))[tid] = (q0 + tid < qcnt) ? g_qidx[q0 + tid] : -1;
            ((float*)(sm + SL_OFF))[tid] = 0.f;
        }
    }
    __syncthreads();

    const __nv_bfloat16* Kg = g_Kh + (size_t)b * NPIX * DDIM;
    const __nv_bfloat16* Fg = g_Fh + (size_t)b * NPIX * DDIM;
    const int ntt = (kcnt + 63) >> 6;
    const int ntg = (g == 0) ? ((ntt + 1) >> 1) : (ntt >> 1);

    const uint32_t Kbase = sb + KOFF + g * 32768;
    const uint32_t Fbase = sb + FOFF + g * 32768;
    const uint32_t Pbase = sb + POFF + g * 8192;
    const int barid = 1 + g;

    // GEMM1 fragment constants
    const int aRow0 = qh * 32 + (lane & 15);           // slab 0 row
    const int aCb   = lane >> 4;
    const int bRowOff = (lane & 7) + ((lane >> 4) << 3);
    const int bCb   = (lane >> 3) & 1;
    // GEMM2 fragment constants
    const int pRow  = lane & 15;                        // + s*16
    const int pCb   = lane >> 4;
    const int fRowOff = (lane & 7) + (((lane >> 3) & 1) << 3);
    const int fCb   = (lane >> 4) & 1;

    float o[32][4];
    #pragma unroll
    for (int j = 0; j < 32; j++) { o[j][0] = o[j][1] = o[j][2] = o[j][3] = 0.f; }
    float la[2][2] = {{0.f, 0.f}, {0.f, 0.f}};          // [slab][rowhalf] partial l

    if (ntg > 0) { STAGE_TILE(Kg, Kbase, g * 64); STAGE_TILE(Fg, Fbase, g * 64); }

    for (int t = 0; t < ntg; t++) {
        const int k0 = (g + 2 * t) * 64;

        asm volatile("cp.async.wait_group 1;" ::: "memory");     // K_t ready (F_t may pend)
        asm volatile("bar.sync %0, 128;" :: "r"(barid) : "memory");

        // ---------- GEMM1: warp computes S[32q x 32k] ----------
        float s[2][4][4];
        #pragma unroll
        for (int i = 0; i < 2; i++)
            #pragma unroll
            for (int j = 0; j < 4; j++)
                s[i][j][0] = s[i][j][1] = s[i][j][2] = s[i][j][3] = 0.f;

        #pragma unroll
        for (int ks = 0; ks < 16; ks++) {
            uint32_t a[2][4];
            #pragma unroll
            for (int sl = 0; sl < 2; sl++) {
                int row = aRow0 + sl * 16;
                ldsm4(a[sl][0], a[sl][1], a[sl][2], a[sl][3],
                      sb + QOFF + row * 512 + (((2 * ks + aCb) ^ (row & 7)) << 4));
            }
            #pragma unroll
            for (int nc = 0; nc < 2; nc++) {
                int row = kh * 32 + nc * 16 + bRowOff;
                uint32_t r0, r1, r2, r3;
                ldsm4(r0, r1, r2, r3, Kbase + row * 512 + (((2 * ks + bCb) ^ (row & 7)) << 4));
                #pragma unroll
                for (int sl = 0; sl < 2; sl++) {
                    mma16816(s[sl][2 * nc],     a[sl][0], a[sl][1], a[sl][2], a[sl][3], r0, r1);
                    mma16816(s[sl][2 * nc + 1], a[sl][0], a[sl][1], a[sl][2], a[sl][3], r2, r3);
                }
            }
        }

        // ---------- exp (bounded scores -> no max), l accum, P -> smem ----------
        const bool tail = (k0 + 64 > kcnt);
        #pragma unroll
        for (int sl = 0; sl < 2; sl++) {
            int qrow = qh * 32 + sl * 16 + (lane >> 2);
            #pragma unroll
            for (int j = 0; j < 4; j++) {
                int nc = j >> 1, h = j & 1;
                float e0, e1, e2, e3;
                if (tail) {
                    int kb = k0 + kh * 32 + nc * 16 + h * 8 + 2 * (lane & 3);
                    e0 = (kb     < kcnt) ? __expf(s[sl][j][0]) : 0.f;
                    e1 = (kb + 1 < kcnt) ? __expf(s[sl][j][1]) : 0.f;
                    e2 = (kb     < kcnt) ? __expf(s[sl][j][2]) : 0.f;
                    e3 = (kb + 1 < kcnt) ? __expf(s[sl][j][3]) : 0.f;
                } else {
                    e0 = __expf(s[sl][j][0]);
                    e1 = __expf(s[sl][j][1]);
                    e2 = __expf(s[sl][j][2]);
                    e3 = __expf(s[sl][j][3]);
                }
                la[sl][0] += e0 + e1;
                la[sl][1] += e2 + e3;
                int unit = kh * 4 + nc * 2 + h;
                uint32_t a0 = Pbase + qrow * 128 + ((unit ^ (qrow & 7)) << 4) + ((lane & 3) << 2);
                int qrow1 = qrow + 8;
                uint32_t a1 = Pbase + qrow1 * 128 + ((unit ^ (qrow1 & 7)) << 4) + ((lane & 3) << 2);
                *(uint32_t*)(sm + (a0 - sb)) = pack_bf2(e0, e1);
                *(uint32_t*)(sm + (a1 - sb)) = pack_bf2(e2, e3);
            }
        }

        // F_t ready; combined barrier: K consumed + P visible + F ready
        asm volatile("cp.async.wait_group 0;" ::: "memory");
        asm volatile("bar.sync %0, 128;" :: "r"(barid) : "memory");
        if (t + 1 < ntg) STAGE_TILE(Kg, Kbase, (g + 2 * (t + 1)) * 64);

        // ---------- GEMM2: warp owns d-section [wg*64, wg*64+64), all 64 q ----------
        #pragma unroll
        for (int kk = 0; kk < 4; kk++) {
            uint32_t ap[4][4];
            #pragma unroll
            for (int sl = 0; sl < 4; sl++) {
                int row = sl * 16 + pRow;
                ldsm4(ap[sl][0], ap[sl][1], ap[sl][2], ap[sl][3],
                      Pbase + row * 128 + (((2 * kk + pCb) ^ (row & 7)) << 4));
            }
            #pragma unroll
            for (int nb = 0; nb < 4; nb++) {
                int pg = wg * 4 + nb;                   // d16 block
                int row = kk * 16 + fRowOff;
                uint32_t r0, r1, r2, r3;
                ldsm4t(r0, r1, r2, r3, Fbase + row * 512 + (((2 * pg + fCb) ^ (row & 7)) << 4));
                #pragma unroll
                for (int sl = 0; sl < 4; sl++) {
                    mma16816(o[sl * 8 + 2 * nb],     ap[sl][0], ap[sl][1], ap[sl][2], ap[sl][3], r0, r1);
                    mma16816(o[sl * 8 + 2 * nb + 1], ap[sl][0], ap[sl][1], ap[sl][2], ap[sl][3], r2, r3);
                }
            }
        }

        asm volatile("bar.sync %0, 128;" :: "r"(barid) : "memory"); // F + P consumed
        if (t + 1 < ntg) STAGE_TILE(Fg, Fbase, (g + 2 * (t + 1)) * 64);
    }

    // ---------- l: quad-reduce, add into shared ----------
    #pragma unroll
    for (int sl = 0; sl < 2; sl++)
        #pragma unroll
        for (int rh = 0; rh < 2; rh++) {
            float v = la[sl][rh];
            v += __shfl_xor_sync(0xffffffffu, v, 1);
            v += __shfl_xor_sync(0xffffffffu, v, 2);
            la[sl][rh] = v;
        }
    if ((lane & 3) == 0) {
        float* slp = (float*)(sm + SL_OFF);
        #pragma unroll
        for (int sl = 0; sl < 2; sl++)
            #pragma unroll
            for (int rh = 0; rh < 2; rh++)
                atomicAdd(&slp[qh * 32 + sl * 16 + rh * 8 + (lane >> 2)], la[sl][rh]);
    }
    __syncthreads();   // l complete; K/F regions retired -> Obuf reuse safe

    // ---------- O merge: group1 writes, group0 adds+scales ----------
    float* Ob = (float*)(sm + OB_OFF);
    if (g == 1) {
        #pragma unroll
        for (int sl = 0; sl < 4; sl++) {
            int q = sl * 16 + (lane >> 2);
            #pragma unroll
            for (int nb2 = 0; nb2 < 8; nb2++) {
                int d = wg * 64 + nb2 * 8 + 2 * (lane & 3);
                *(float2*)(Ob + q * OSTRIDE + d)       = make_float2(o[sl*8+nb2][0], o[sl*8+nb2][1]);
                *(float2*)(Ob + (q + 8) * OSTRIDE + d) = make_float2(o[sl*8+nb2][2], o[sl*8+nb2][3]);
            }
        }
    }
    __syncthreads();
    if (g == 0) {
        const float* slp = (const float*)(sm + SL_OFF);
        #pragma unroll
        for (int sl = 0; sl < 4; sl++) {
            int q = sl * 16 + (lane >> 2);
            float il0 = 1.0f / slp[q];
            float il1 = 1.0f / slp[q + 8];
            #pragma unroll
            for (int nb2 = 0; nb2 < 8; nb2++) {
                int d = wg * 64 + nb2 * 8 + 2 * (lane & 3);
                float2 x0 = *(float2*)(Ob + q * OSTRIDE + d);
                float2 x1 = *(float2*)(Ob + (q + 8) * OSTRIDE + d);
                *(float2*)(Ob + q * OSTRIDE + d) =
                    make_float2((o[sl*8+nb2][0] + x0.x) * il0, (o[sl*8+nb2][1] + x0.y) * il0);
                *(float2*)(Ob + (q + 8) * OSTRIDE + d) =
                    make_float2((o[sl*8+nb2][2] + x1.x) * il1, (o[sl*8+nb2][3] + x1.y) * il1);
            }
        }
    }
    __syncthreads();

    // ---------- coalesced scatter into hole columns ----------
    {
        const int q = tid & 63;
        const int n = ((const int*)(sm + QN_OFF))[q];
        float* ob = out + ((size_t)b * 768 + 512) * NPIX;
        if (n >= 0) {
            for (int r = tid >> 6; r < 256; r += 4)
                ob[(size_t)r * NPIX + n] = Ob[q * OSTRIDE + r];
        }
    }
}

// ---------------- launch ------------------------------------------------------
extern "C" void kernel_launch(void* const* d_in, const int* in_sizes, int n_in,
                              void* d_out, int out_size)
{
    const float* x    = (const float*)d_in[0];
    const void*  mask = d_in[1];
    float*       out  = (float*)d_out;

    const int N = in_sizes[1];                  // 4096
    const int B = in_sizes[0] / (512 * N);      // 8

    k_compact<<<1, 128>>>(mask, N);
    k_prep<<<dim3(N / 32, B), 256>>>(x, out);
    cudaFuncSetAttribute(k_attn, cudaFuncAttributeMaxDynamicSharedMemorySize, SMB);
    k_attn<<<dim3(N / 64, B), 256, SMB>>>(out);
}